// round 13
// baseline (speedup 1.0000x reference)
#include <cuda_runtime.h>
#include <cuda_bf16.h>
#include <math.h>
#include <cstdint>

using u32 = unsigned int;
using u64 = unsigned long long;
typedef __nv_bfloat16 bf16;

// Problem constants
#define B_   128
#define T_   200
#define TM1  199
#define NQP1 5001
#define NPAD 5120
#define NTOK  (B_ * T_)    // 25600
#define NTOK1 (B_ * TM1)   // 25472

#define SMEM_128 98304     // 128-wide core: 3 x (16KB A + 16KB B)
#define SMEM_256 147456    // 256-wide core: 3 x (16KB A + 32KB B)

// ---------------------------------------------------------------------------
// Device scratch (bf16 split layouts: A-side = [hi|lo|hi], B-side = [hi|hi|lo])
// ---------------------------------------------------------------------------
__device__ __align__(16) bf16  g_qa3  [(size_t)NTOK  * 768];
__device__ __align__(16) bf16  g_qe3  [(size_t)NTOK  * 384];
__device__ __align__(16) bf16  g_t13  [(size_t)NTOK  * 384];
__device__ __align__(16) bf16  g_t23  [(size_t)NTOK  * 384];
__device__ __align__(16) bf16  g_rk3  [(size_t)NTOK  * 384];
__device__ __align__(16) float g_logits[NTOK  *  64];
__device__ __align__(16) float g_corr  [NTOK  *  64];
__device__ __align__(16) float g_erase [NTOK  * 128];
__device__ __align__(16) float g_add   [NTOK  * 128];
__device__ __align__(16) float g_rc    [NTOK1 * 128];
__device__ __align__(16) float g_rcn   [NTOK1 * 128];
__device__ __align__(16) bf16  g_beh3 [(size_t)NTOK1 * 768];
__device__ __align__(16) bf16  g_mas3 [(size_t)NTOK1 * 768];
__device__ __align__(16) float g_hs    [NTOK1 * 256];
__device__ __align__(16) bf16  g_A3   [(size_t)NTOK1 * 768];
__device__ __align__(16) bf16  g_B3   [(size_t)NPAD  * 768];
// split weights (B-side layout)
__device__ __align__(16) bf16  g_We3 [128 * 768];
__device__ __align__(16) bf16  g_Wa3 [128 * 768];
__device__ __align__(16) bf16  g_We23[128 * 384];
__device__ __align__(16) bf16  g_Wa23[128 * 384];
__device__ __align__(16) bf16  g_Wk3 [128 * 384];
__device__ __align__(16) bf16  g_key3[128 * 384];
__device__ __align__(16) bf16  g_Wsb3[256 * 768];
__device__ __align__(16) bf16  g_Ws3 [256 * 768];

// ---------------------------------------------------------------------------
// mma.sync helpers (verified rounds 7-12)
// ---------------------------------------------------------------------------
__device__ __forceinline__ void mma16816(float c[4], const u32 a[4],
                                         u32 b0, u32 b1)
{
    asm volatile(
        "mma.sync.aligned.m16n8k16.row.col.f32.bf16.bf16.f32 "
        "{%0,%1,%2,%3}, {%4,%5,%6,%7}, {%8,%9}, {%0,%1,%2,%3};\n"
        : "+f"(c[0]), "+f"(c[1]), "+f"(c[2]), "+f"(c[3])
        : "r"(a[0]), "r"(a[1]), "r"(a[2]), "r"(a[3]), "r"(b0), "r"(b1));
}
__device__ __forceinline__ u32 saddr(const void* p)
{
    return (u32)__cvta_generic_to_shared(p);
}
__device__ __forceinline__ void cp16(u32 d, const void* s)
{
    asm volatile("cp.async.cg.shared.global [%0], [%1], 16;\n" :: "r"(d), "l"(s));
}
// SW128 swizzled byte offset: 16B chunk c (0..7) in a 128B row
__device__ __forceinline__ u32 sw16(int row, int c)
{
    return (u32)(row * 128 + (((c ^ row) & 7) << 4));
}
__device__ __forceinline__ float act_f(float v, int ACT)
{
    if (ACT == 1) return 1.f / (1.f + __expf(-v));
    if (ACT == 2) return tanhf(v);
    return v;
}

struct GArgs {
    const bf16* A; const bf16* B; const float* bias;
    float* Cf; bf16* Cs;
    int ldc, N, splitW, NST, ACT, EPI;
};

// split-store helper (EPI 1): write [hi|lo|hi] pair at row m, col n
__device__ __forceinline__ void split_store(bf16* Cs, int splitW, int m, int n,
                                            float v0, float v1)
{
    bf16 h0 = __float2bfloat16(v0);
    bf16 h1 = __float2bfloat16(v1);
    bf16 l0 = __float2bfloat16(v0 - __bfloat162float(h0));
    bf16 l1 = __float2bfloat16(v1 - __bfloat162float(h1));
    size_t b = (size_t)m * 3 * splitW;
    __nv_bfloat162 H; H.x = h0; H.y = h1;
    __nv_bfloat162 L; L.x = l0; L.y = l1;
    *reinterpret_cast<__nv_bfloat162*>(&Cs[b + n])              = H;
    *reinterpret_cast<__nv_bfloat162*>(&Cs[b + splitW + n])     = L;
    *reinterpret_cast<__nv_bfloat162*>(&Cs[b + 2 * splitW + n]) = H;
}

// ---------------------------------------------------------------------------
// 128x128 CTA tile core (verified round 12). occ 2.
// ---------------------------------------------------------------------------
__device__ __forceinline__ void mma_core128(const GArgs ga, int m0, int n0)
{
    extern __shared__ bf16 smbuf[];
    const int NST = ga.NST;
    const int KW  = NST * 64;

    const int tid  = threadIdx.x;
    const int lane = tid & 31, wid = tid >> 5;
    const int wm = wid & 1, wn = wid >> 1;

    float acc[4][4][4];
#pragma unroll
    for (int mt = 0; mt < 4; mt++)
#pragma unroll
        for (int nt = 0; nt < 4; nt++)
#pragma unroll
            for (int r = 0; r < 4; r++) acc[mt][nt][r] = 0.f;

    const bf16* Ag = ga.A + (size_t)m0 * KW;
    const bf16* Bg = ga.B + (size_t)n0 * KW;

    const int lr8 = (lane & 7) + ((lane >> 3) & 1) * 8;
    const int cq  = lane >> 4;

    const u32 ab0 = saddr(smbuf);
    const u32 bb0 = ab0 + 49152;

#define LOAD128(buf, k0)                                                   \
    do {                                                                   \
        u32 ab = ab0 + (buf) * 16384;                                      \
        u32 bb = bb0 + (buf) * 16384;                                      \
        _Pragma("unroll")                                                  \
        for (int i = 0; i < 4; i++) {                                      \
            int g = tid + i * 256;                                         \
            int row = g >> 3, c = g & 7;                                   \
            cp16(ab + sw16(row, c), Ag + (size_t)row * KW + (k0) + c * 8); \
            cp16(bb + sw16(row, c), Bg + (size_t)row * KW + (k0) + c * 8); \
        }                                                                  \
        asm volatile("cp.async.commit_group;\n");                          \
    } while (0)

    LOAD128(0, 0);
    LOAD128(1, 64);

    for (int st = 0; st < NST; st++) {
        if (st < NST - 1)
            asm volatile("cp.async.wait_group 1;\n");
        else
            asm volatile("cp.async.wait_group 0;\n");
        __syncthreads();
        if (st + 2 < NST)
            LOAD128((st + 2) % 3, (st + 2) * 64);

        const int buf = st % 3;
        const u32 ab = ab0 + buf * 16384;
        const u32 bb = bb0 + buf * 16384;
#pragma unroll
        for (int ks = 0; ks < 4; ks++) {
            const int chv = ks * 2 + cq;
            u32 af[4][4], bq[4][2];
#pragma unroll
            for (int mt = 0; mt < 4; mt++) {
                u32 ad = ab + sw16(wm * 64 + mt * 16 + lr8, chv);
                asm volatile(
                    "ldmatrix.sync.aligned.m8n8.x4.shared.b16 {%0,%1,%2,%3}, [%4];\n"
                    : "=r"(af[mt][0]), "=r"(af[mt][1]),
                      "=r"(af[mt][2]), "=r"(af[mt][3]) : "r"(ad));
            }
#pragma unroll
            for (int bh = 0; bh < 2; bh++) {
                u32 r0, r1, r2, r3;
                u32 ad = bb + sw16(wn * 32 + bh * 16 + lr8, chv);
                asm volatile(
                    "ldmatrix.sync.aligned.m8n8.x4.shared.b16 {%0,%1,%2,%3}, [%4];\n"
                    : "=r"(r0), "=r"(r1), "=r"(r2), "=r"(r3) : "r"(ad));
                bq[bh * 2 + 0][0] = r0; bq[bh * 2 + 0][1] = r2;
                bq[bh * 2 + 1][0] = r1; bq[bh * 2 + 1][1] = r3;
            }
#pragma unroll
            for (int mt = 0; mt < 4; mt++)
#pragma unroll
                for (int nt = 0; nt < 4; nt++)
                    mma16816(acc[mt][nt], af[mt], bq[nt][0], bq[nt][1]);
        }
    }
#undef LOAD128

    const int gidr = lane >> 2, tig = lane & 3;
#pragma unroll
    for (int nt = 0; nt < 4; nt++) {
        const int n = n0 + wn * 32 + nt * 8 + tig * 2;
        const bool ok0 = (n < ga.N), ok1 = (n + 1 < ga.N);
        const float bA = (ga.bias != nullptr && ok0) ? ga.bias[n] : 0.f;
        const float bB = (ga.bias != nullptr && ok1) ? ga.bias[n + 1] : 0.f;
#pragma unroll
        for (int mt = 0; mt < 4; mt++) {
            const int m = m0 + wm * 64 + mt * 16 + gidr;
            float v00 = act_f(acc[mt][nt][0] + bA, ga.ACT);
            float v01 = act_f(acc[mt][nt][1] + bB, ga.ACT);
            float v10 = act_f(acc[mt][nt][2] + bA, ga.ACT);
            float v11 = act_f(acc[mt][nt][3] + bB, ga.ACT);
            if (ga.EPI == 0) {
                if (ok0) {
                    ga.Cf[(size_t)m * ga.ldc + n]       = v00;
                    ga.Cf[(size_t)(m + 8) * ga.ldc + n] = v10;
                }
                if (ok1) {
                    ga.Cf[(size_t)m * ga.ldc + n + 1]       = v01;
                    ga.Cf[(size_t)(m + 8) * ga.ldc + n + 1] = v11;
                }
            } else if (ok1) {
                split_store(ga.Cs, ga.splitW, m,     n, v00, v01);
                split_store(ga.Cs, ga.splitW, m + 8, n, v10, v11);
            }
        }
    }
}

__global__ void __launch_bounds__(256, 2) mma_fused3(GArgs a0, GArgs a1, GArgs a2)
{
    GArgs ga = (blockIdx.z == 0) ? a0 : (blockIdx.z == 1) ? a1 : a2;
    mma_core128(ga, blockIdx.y * 128, blockIdx.x * 128);
}

// ---------------------------------------------------------------------------
// 128x256 CTA tile core. Warp tile 64x64 (mt 4, nt 8), occ 1 (~200 regs).
// Fewer ldmatrix per MMA (0.25 vs 0.375), half the CTAs, 25% less B traffic.
// ---------------------------------------------------------------------------
__device__ __forceinline__ void mma_core256(const GArgs ga, int m0, int n0)
{
    extern __shared__ bf16 smbuf[];
    const int NST = ga.NST;
    const int KW  = NST * 64;

    const int tid  = threadIdx.x;
    const int lane = tid & 31, wid = tid >> 5;
    const int wm = wid & 1, wn = wid >> 1;   // warp tile 64(M) x 64(N)

    float acc[4][8][4];
#pragma unroll
    for (int mt = 0; mt < 4; mt++)
#pragma unroll
        for (int nt = 0; nt < 8; nt++)
#pragma unroll
            for (int r = 0; r < 4; r++) acc[mt][nt][r] = 0.f;

    const bf16* Ag = ga.A + (size_t)m0 * KW;
    const bf16* Bg = ga.B + (size_t)n0 * KW;

    const int lr8 = (lane & 7) + ((lane >> 3) & 1) * 8;
    const int cq  = lane >> 4;

    const u32 ab0 = saddr(smbuf);            // A stages: +buf*16384 (16KB)
    const u32 bb0 = ab0 + 49152;             // B stages: +buf*32768 (32KB)

#define LOAD256(buf, k0)                                                   \
    do {                                                                   \
        u32 ab = ab0 + (buf) * 16384;                                      \
        u32 bb = bb0 + (buf) * 32768;                                      \
        _Pragma("unroll")                                                  \
        for (int i = 0; i < 4; i++) {                                      \
            int g = tid + i * 256;                                         \
            int row = g >> 3, c = g & 7;                                   \
            cp16(ab + sw16(row, c), Ag + (size_t)row * KW + (k0) + c * 8); \
        }                                                                  \
        _Pragma("unroll")                                                  \
        for (int i = 0; i < 8; i++) {                                      \
            int g = tid + i * 256;                                         \
            int row = g >> 3, c = g & 7;                                   \
            cp16(bb + sw16(row, c), Bg + (size_t)row * KW + (k0) + c * 8); \
        }                                                                  \
        asm volatile("cp.async.commit_group;\n");                          \
    } while (0)

    LOAD256(0, 0);
    LOAD256(1, 64);

    for (int st = 0; st < NST; st++) {
        if (st < NST - 1)
            asm volatile("cp.async.wait_group 1;\n");
        else
            asm volatile("cp.async.wait_group 0;\n");
        __syncthreads();
        if (st + 2 < NST)
            LOAD256((st + 2) % 3, (st + 2) * 64);

        const int buf = st % 3;
        const u32 ab = ab0 + buf * 16384;
        const u32 bb = bb0 + buf * 32768;
#pragma unroll
        for (int ks = 0; ks < 4; ks++) {
            const int chv = ks * 2 + cq;
            u32 af[4][4], bq[8][2];
#pragma unroll
            for (int mt = 0; mt < 4; mt++) {
                u32 ad = ab + sw16(wm * 64 + mt * 16 + lr8, chv);
                asm volatile(
                    "ldmatrix.sync.aligned.m8n8.x4.shared.b16 {%0,%1,%2,%3}, [%4];\n"
                    : "=r"(af[mt][0]), "=r"(af[mt][1]),
                      "=r"(af[mt][2]), "=r"(af[mt][3]) : "r"(ad));
            }
#pragma unroll
            for (int bh = 0; bh < 4; bh++) {
                u32 r0, r1, r2, r3;
                u32 ad = bb + sw16(wn * 64 + bh * 16 + lr8, chv);
                asm volatile(
                    "ldmatrix.sync.aligned.m8n8.x4.shared.b16 {%0,%1,%2,%3}, [%4];\n"
                    : "=r"(r0), "=r"(r1), "=r"(r2), "=r"(r3) : "r"(ad));
                bq[bh * 2 + 0][0] = r0; bq[bh * 2 + 0][1] = r2;
                bq[bh * 2 + 1][0] = r1; bq[bh * 2 + 1][1] = r3;
            }
#pragma unroll
            for (int mt = 0; mt < 4; mt++)
#pragma unroll
                for (int nt = 0; nt < 8; nt++)
                    mma16816(acc[mt][nt], af[mt], bq[nt][0], bq[nt][1]);
        }
    }
#undef LOAD256

    const int gidr = lane >> 2, tig = lane & 3;
#pragma unroll
    for (int nt = 0; nt < 8; nt++) {
        const int n = n0 + wn * 64 + nt * 8 + tig * 2;
        const bool ok0 = (n < ga.N), ok1 = (n + 1 < ga.N);
        const float bA = (ga.bias != nullptr && ok0) ? ga.bias[n] : 0.f;
        const float bB = (ga.bias != nullptr && ok1) ? ga.bias[n + 1] : 0.f;
#pragma unroll
        for (int mt = 0; mt < 4; mt++) {
            const int m = m0 + wm * 64 + mt * 16 + gidr;
            float v00 = act_f(acc[mt][nt][0] + bA, ga.ACT);
            float v01 = act_f(acc[mt][nt][1] + bB, ga.ACT);
            float v10 = act_f(acc[mt][nt][2] + bA, ga.ACT);
            float v11 = act_f(acc[mt][nt][3] + bB, ga.ACT);
            if (ga.EPI == 0) {
                if (ok0) {
                    ga.Cf[(size_t)m * ga.ldc + n]       = v00;
                    ga.Cf[(size_t)(m + 8) * ga.ldc + n] = v10;
                }
                if (ok1) {
                    ga.Cf[(size_t)m * ga.ldc + n + 1]       = v01;
                    ga.Cf[(size_t)(m + 8) * ga.ldc + n + 1] = v11;
                }
            } else if (ok1) {
                split_store(ga.Cs, ga.splitW, m,     n, v00, v01);
                split_store(ga.Cs, ga.splitW, m + 8, n, v10, v11);
            }
        }
    }
}

__global__ void __launch_bounds__(256, 1) mma_one256(GArgs ga)
{
    mma_core256(ga, blockIdx.y * 128, blockIdx.x * 256);
}

__global__ void __launch_bounds__(256, 1) mma_fused256_2(GArgs a0, GArgs a1)
{
    GArgs ga = (blockIdx.z == 0) ? a0 : a1;
    mma_core256(ga, blockIdx.y * 128, blockIdx.x * 256);
}

// ---------------------------------------------------------------------------
// Weight split (B-side [hi|hi|lo]); rows >= Nw zeroed.
// ---------------------------------------------------------------------------
__global__ void convW_kernel(const float* __restrict__ X, bf16* __restrict__ Y,
                             int Nw, int K)
{
    int idx = blockIdx.x * 256 + threadIdx.x;
    int r = idx / K, c = idx - r * K;
    float x = (r < Nw) ? X[(size_t)r * K + c] : 0.f;
    bf16 h = __float2bfloat16(x);
    bf16 l = __float2bfloat16(x - __bfloat162float(h));
    size_t base = (size_t)r * 3 * K;
    Y[base + c] = h; Y[base + K + c] = h; Y[base + 2 * K + c] = l;
}

// ---------------------------------------------------------------------------
// Gather -> qa3 [25600,768] and qe3 [25600,384], A-side split
// ---------------------------------------------------------------------------
__global__ void gather3_kernel(const int* __restrict__ q, const int* __restrict__ a,
                               const float* __restrict__ qet, const float* __restrict__ aet,
                               bf16* __restrict__ qa3, bf16* __restrict__ qe3)
{
    int tok = blockIdx.x;
    int i   = threadIdx.x;
    float v = (i < 128) ? qet[(size_t)q[tok] * 128 + i]
                        : aet[(size_t)a[tok] * 128 + (i - 128)];
    bf16 h = __float2bfloat16(v);
    bf16 l = __float2bfloat16(v - __bfloat162float(h));
    size_t b7 = (size_t)tok * 768;
    qa3[b7 + i] = h; qa3[b7 + 256 + i] = l; qa3[b7 + 512 + i] = h;
    if (i < 128) {
        size_t b3 = (size_t)tok * 384;
        qe3[b3 + i] = h; qe3[b3 + 128 + i] = l; qe3[b3 + 256 + i] = h;
    }
}

// ---------------------------------------------------------------------------
// behavior/mastery concat -> A-side split beh3/mas3 [25472,768]
// ---------------------------------------------------------------------------
__global__ void behmas3_kernel(const float* __restrict__ rc, const float* __restrict__ rcn,
                               const bf16* __restrict__ qa3,
                               bf16* __restrict__ beh3, bf16* __restrict__ mas3)
{
    int tok = blockIdx.x;
    int i   = threadIdx.x;
    int b   = tok / TM1;
    int t   = tok - b * TM1;
    float vb, vm;
    if (i < 128) {
        vb = rc [(size_t)tok * 128 + i];
        vm = rcn[(size_t)tok * 128 + i];
    } else {
        int c = i - 128;
        size_t r0 = (size_t)(b * T_ + t) * 768;
        size_t r1 = (size_t)(b * T_ + t + 1) * 768;
        vb = __bfloat162float(qa3[r0 + c]) + __bfloat162float(qa3[r0 + 256 + c]);
        vm = __bfloat162float(qa3[r1 + c]) + __bfloat162float(qa3[r1 + 256 + c]);
    }
    bf16 hb = __float2bfloat16(vb);
    bf16 lb = __float2bfloat16(vb - __bfloat162float(hb));
    bf16 hm = __float2bfloat16(vm);
    bf16 lm = __float2bfloat16(vm - __bfloat162float(hm));
    size_t o = (size_t)tok * 768;
    beh3[o + i] = hb; beh3[o + 256 + i] = lb; beh3[o + 512 + i] = hb;
    mas3[o + i] = hm; mas3[o + 256 + i] = lm; mas3[o + 512 + i] = hm;
}

// ---------------------------------------------------------------------------
// softmax / scan / pred (verified, unchanged)
// ---------------------------------------------------------------------------
__global__ void softmax64_kernel(const float* __restrict__ lg, float* __restrict__ co,
                                 int ntok)
{
    int g    = blockIdx.x * blockDim.x + threadIdx.x;
    int w    = g >> 5;
    int lane = g & 31;
    if (w >= ntok) return;
    const float* L = lg + (size_t)w * 64;
    float v0 = L[lane], v1 = L[lane + 32];
    float mx = fmaxf(v0, v1);
#pragma unroll
    for (int o = 16; o; o >>= 1) mx = fmaxf(mx, __shfl_xor_sync(0xffffffffu, mx, o));
    float e0 = __expf(v0 - mx), e1 = __expf(v1 - mx);
    float s = e0 + e1;
#pragma unroll
    for (int o = 16; o; o >>= 1) s += __shfl_xor_sync(0xffffffffu, s, o);
    float inv = 1.f / s;
    co[(size_t)w * 64 + lane]      = e0 * inv;
    co[(size_t)w * 64 + lane + 32] = e1 * inv;
}

__global__ void __launch_bounds__(256) scan_kernel(
    const float* __restrict__ corr, const float* __restrict__ er,
    const float* __restrict__ ad,   const float* __restrict__ vinit,
    float* __restrict__ rc, float* __restrict__ rcn)
{
    int b   = blockIdx.x;
    int tid = threadIdx.x;
    int v   = tid & 127;
    int cg  = tid >> 7;

    float M[32];
#pragma unroll
    for (int i = 0; i < 32; i++) M[i] = vinit[(size_t)(cg * 32 + i) * 128 + v];

    __shared__ float sw[64], swn[64], s_rc[128], s_rcn[128];

    const float* corr_b = corr + (size_t)b * T_ * 64;
    const float* er_b   = er   + (size_t)b * T_ * 128;
    const float* ad_b   = ad   + (size_t)b * T_ * 128;
    float* rc_b  = rc  + (size_t)b * TM1 * 128;
    float* rcn_b = rcn + (size_t)b * TM1 * 128;

    float ev_n = er_b[v];
    float av_n = ad_b[v];

    for (int t = 0; t < TM1; t++) {
        float ev = ev_n, av = av_n;
        if (t + 1 < TM1) {
            ev_n = er_b[(size_t)(t + 1) * 128 + v];
            av_n = ad_b[(size_t)(t + 1) * 128 + v];
        }
        if (tid < 64)       sw[tid]       = corr_b[(size_t)t * 64 + tid];
        else if (tid < 128) swn[tid - 64] = corr_b[(size_t)(t + 1) * 64 + (tid - 64)];
        __syncthreads();

        float prc = 0.f, prcn = 0.f;
#pragma unroll
        for (int i = 0; i < 32; i++) {
            float wc = sw[cg * 32 + i];
            float m  = fmaf(wc, av, M[i] * (1.f - wc * ev));
            M[i] = m;
            prc  = fmaf(wc, m, prc);
            prcn = fmaf(swn[cg * 32 + i], m, prcn);
        }
        if (cg == 0) { s_rc[v] = prc; s_rcn[v] = prcn; }
        __syncthreads();
        if (cg == 1) {
            rc_b [(size_t)t * 128 + v] = s_rc[v]  + prc;
            rcn_b[(size_t)t * 128 + v] = s_rcn[v] + prcn;
        }
        __syncthreads();
    }
}

__global__ void pred_kernel(const float* __restrict__ hs, const float* __restrict__ Wo,
                            const float* __restrict__ bo, float* __restrict__ out, int ntok)
{
    int g    = blockIdx.x * blockDim.x + threadIdx.x;
    int w    = g >> 5;
    int lane = g & 31;
    if (w >= ntok) return;
    const float* h = hs + (size_t)w * 256;
    float s = 0.f;
#pragma unroll
    for (int j = 0; j < 8; j++) s = fmaf(h[lane + j * 32], Wo[lane + j * 32], s);
#pragma unroll
    for (int o = 16; o; o >>= 1) s += __shfl_xor_sync(0xffffffffu, s, o);
    if (lane == 0) out[w] = 1.f / (1.f + __expf(-(s + bo[0])));
}

// ---------------------------------------------------------------------------
// Launch
// ---------------------------------------------------------------------------
extern "C" void kernel_launch(void* const* d_in, const int* in_sizes, int n_in,
                              void* d_out, int out_size)
{
    (void)in_sizes; (void)n_in; (void)out_size;

    const int*   q_data     = (const int*)  d_in[0];
    const int*   a_data     = (const int*)  d_in[1];
    const float* q_embed    = (const float*)d_in[2];
    const float* a_embed    = (const float*)d_in[3];
    const float* key_matrix = (const float*)d_in[4];
    const float* value_init = (const float*)d_in[5];
    const float* Wk  = (const float*)d_in[6];   const float* bk  = (const float*)d_in[7];
    const float* We  = (const float*)d_in[8];   const float* be  = (const float*)d_in[9];
    const float* We2 = (const float*)d_in[10];  const float* be2 = (const float*)d_in[11];
    const float* Wa  = (const float*)d_in[12];  const float* ba  = (const float*)d_in[13];
    const float* Wa2 = (const float*)d_in[14];  const float* ba2 = (const float*)d_in[15];
    const float* Ws  = (const float*)d_in[16];  const float* bs  = (const float*)d_in[17];
    const float* Wo  = (const float*)d_in[18];  const float* bo  = (const float*)d_in[19];
    const float* Wsb = (const float*)d_in[20];  const float* bsb = (const float*)d_in[21];
    const float* Wob = (const float*)d_in[22];  const float* bob = (const float*)d_in[23];
    float* out = (float*)d_out;

    bf16 *p_qa3, *p_qe3, *p_t13, *p_t23, *p_rk3, *p_beh3, *p_mas3, *p_A3, *p_B3;
    bf16 *p_We3, *p_Wa3, *p_We23, *p_Wa23, *p_Wk3, *p_key3, *p_Wsb3, *p_Ws3;
    float *p_log, *p_corr, *p_er, *p_ad, *p_rc, *p_rcn, *p_hs;
    cudaGetSymbolAddress((void**)&p_qa3,  g_qa3);
    cudaGetSymbolAddress((void**)&p_qe3,  g_qe3);
    cudaGetSymbolAddress((void**)&p_t13,  g_t13);
    cudaGetSymbolAddress((void**)&p_t23,  g_t23);
    cudaGetSymbolAddress((void**)&p_rk3,  g_rk3);
    cudaGetSymbolAddress((void**)&p_log,  g_logits);
    cudaGetSymbolAddress((void**)&p_corr, g_corr);
    cudaGetSymbolAddress((void**)&p_er,   g_erase);
    cudaGetSymbolAddress((void**)&p_ad,   g_add);
    cudaGetSymbolAddress((void**)&p_rc,   g_rc);
    cudaGetSymbolAddress((void**)&p_rcn,  g_rcn);
    cudaGetSymbolAddress((void**)&p_beh3, g_beh3);
    cudaGetSymbolAddress((void**)&p_mas3, g_mas3);
    cudaGetSymbolAddress((void**)&p_hs,   g_hs);
    cudaGetSymbolAddress((void**)&p_A3,   g_A3);
    cudaGetSymbolAddress((void**)&p_B3,   g_B3);
    cudaGetSymbolAddress((void**)&p_We3,  g_We3);
    cudaGetSymbolAddress((void**)&p_Wa3,  g_Wa3);
    cudaGetSymbolAddress((void**)&p_We23, g_We23);
    cudaGetSymbolAddress((void**)&p_Wa23, g_Wa23);
    cudaGetSymbolAddress((void**)&p_Wk3,  g_Wk3);
    cudaGetSymbolAddress((void**)&p_key3, g_key3);
    cudaGetSymbolAddress((void**)&p_Wsb3, g_Wsb3);
    cudaGetSymbolAddress((void**)&p_Ws3,  g_Ws3);

    cudaFuncSetAttribute(mma_fused3,    cudaFuncAttributeMaxDynamicSharedMemorySize, SMEM_128);
    cudaFuncSetAttribute(mma_one256,    cudaFuncAttributeMaxDynamicSharedMemorySize, SMEM_256);
    cudaFuncSetAttribute(mma_fused256_2, cudaFuncAttributeMaxDynamicSharedMemorySize, SMEM_256);

    // ---- weight splits ----
    convW_kernel<<<128 * 256 / 256, 256>>>(We,  p_We3, 128, 256);
    convW_kernel<<<128 * 256 / 256, 256>>>(Wa,  p_Wa3, 128, 256);
    convW_kernel<<<128 * 128 / 256, 256>>>(We2, p_We23, 128, 128);
    convW_kernel<<<128 * 128 / 256, 256>>>(Wa2, p_Wa23, 128, 128);
    convW_kernel<<<128 * 128 / 256, 256>>>(Wk,  p_Wk3, 128, 128);
    convW_kernel<<<128 * 128 / 256, 256>>>(key_matrix, p_key3, 64, 128);
    convW_kernel<<<256 * 256 / 256, 256>>>(Wsb, p_Wsb3, 256, 256);
    convW_kernel<<<256 * 256 / 256, 256>>>(Ws,  p_Ws3, 256, 256);
    convW_kernel<<<NPAD * 256 / 256, 256>>>(Wob, p_B3, NQP1, 256);

    // ---- gather ----
    gather3_kernel<<<NTOK, 256>>>(q_data, a_data, q_embed, a_embed, p_qa3, p_qe3);

    // ---- stage A: t1 | t2 | rk in one launch ----
    {
        GArgs a0 = { p_qa3, p_We3, be, nullptr, p_t13, 0, 128, 128, 12, 0, 1 };
        GArgs a1 = { p_qa3, p_Wa3, ba, nullptr, p_t23, 0, 128, 128, 12, 0, 1 };
        GArgs a2 = { p_qe3, p_Wk3, bk, nullptr, p_rk3, 0, 128, 128,  6, 0, 1 };
        mma_fused3<<<dim3(1, NTOK / 128, 3), 256, SMEM_128>>>(a0, a1, a2);
    }
    // ---- stage A: er | ad | logits in one launch ----
    {
        GArgs a0 = { p_t13, p_We23, be2, p_er,  nullptr, 128, 128, 0, 6, 1, 0 };
        GArgs a1 = { p_t23, p_Wa23, ba2, p_ad,  nullptr, 128, 128, 0, 6, 2, 0 };
        GArgs a2 = { p_rk3, p_key3, nullptr, p_log, nullptr, 64, 64, 0, 6, 0, 0 };
        mma_fused3<<<dim3(1, NTOK / 128, 3), 256, SMEM_128>>>(a0, a1, a2);
    }
    softmax64_kernel<<<(NTOK * 32 + 255) / 256, 256>>>(p_log, p_corr, NTOK);

    // ---- stage B: sequential scan ----
    scan_kernel<<<B_, 256>>>(p_corr, p_er, p_ad, value_init, p_rc, p_rcn);

    // ---- stage C: wsb | ws on the 256-wide core ----
    behmas3_kernel<<<NTOK1, 256>>>(p_rc, p_rcn, p_qa3, p_beh3, p_mas3);
    {
        GArgs a0 = { p_beh3, p_Wsb3, bsb, nullptr, p_A3, 0, 256, 256, 12, 2, 1 };
        GArgs a1 = { p_mas3, p_Ws3,  bs,  p_hs,  nullptr, 256, 256, 0, 12, 2, 0 };
        mma_fused256_2<<<dim3(1, NTOK1 / 128, 2), 256, SMEM_256>>>(a0, a1);
    }
    pred_kernel<<<(NTOK1 * 32 + 255) / 256, 256>>>(p_hs, Wo, bo, out, NTOK1);

    // ---- big GEMM last, 128x256 tiles ----
    {
        GArgs ab = { p_A3, p_B3, bob, out + NTOK1, nullptr, NQP1, NQP1, 0, 12, 1, 0 };
        mma_one256<<<dim3(NPAD / 256, NTOK1 / 128), 256, SMEM_256>>>(ab);
    }
}

// round 14
// speedup vs baseline: 1.3075x; 1.3075x over previous
#include <cuda_runtime.h>
#include <cuda_bf16.h>
#include <math.h>
#include <cstdint>

using u32 = unsigned int;
using u64 = unsigned long long;
typedef __nv_bfloat16 bf16;

// Problem constants
#define B_   128
#define T_   200
#define TM1  199
#define NQP1 5001
#define NPAD 5120
#define NTOK  (B_ * T_)    // 25600
#define NTOK1 (B_ * TM1)   // 25472

#define SMEM_128 98304     // 3-stage x (16KB A + 16KB B)

// ---------------------------------------------------------------------------
// Device scratch (bf16 split layouts: A-side = [hi|lo|hi], B-side = [hi|hi|lo])
// ---------------------------------------------------------------------------
__device__ __align__(16) bf16  g_qa3  [(size_t)NTOK  * 768];
__device__ __align__(16) bf16  g_qe3  [(size_t)NTOK  * 384];
__device__ __align__(16) bf16  g_t13  [(size_t)NTOK  * 384];
__device__ __align__(16) bf16  g_t23  [(size_t)NTOK  * 384];
__device__ __align__(16) bf16  g_rk3  [(size_t)NTOK  * 384];
__device__ __align__(16) float g_logits[NTOK  *  64];
__device__ __align__(16) float g_corr  [NTOK  *  64];
__device__ __align__(16) float g_erase [NTOK  * 128];
__device__ __align__(16) float g_add   [NTOK  * 128];
__device__ __align__(16) bf16  g_beh3 [(size_t)NTOK1 * 768];
__device__ __align__(16) bf16  g_mas3 [(size_t)NTOK1 * 768];
__device__ __align__(16) float g_hs    [NTOK1 * 256];
__device__ __align__(16) bf16  g_A3   [(size_t)NTOK1 * 768];
__device__ __align__(16) bf16  g_B3   [(size_t)NPAD  * 768];
// split weights (B-side layout)
__device__ __align__(16) bf16  g_We3 [128 * 768];
__device__ __align__(16) bf16  g_Wa3 [128 * 768];
__device__ __align__(16) bf16  g_We23[128 * 384];
__device__ __align__(16) bf16  g_Wa23[128 * 384];
__device__ __align__(16) bf16  g_Wk3 [128 * 384];
__device__ __align__(16) bf16  g_key3[128 * 384];
__device__ __align__(16) bf16  g_Wsb3[256 * 768];
__device__ __align__(16) bf16  g_Ws3 [256 * 768];

// ---------------------------------------------------------------------------
// mma.sync helpers (verified rounds 7-12)
// ---------------------------------------------------------------------------
__device__ __forceinline__ void mma16816(float c[4], const u32 a[4],
                                         u32 b0, u32 b1)
{
    asm volatile(
        "mma.sync.aligned.m16n8k16.row.col.f32.bf16.bf16.f32 "
        "{%0,%1,%2,%3}, {%4,%5,%6,%7}, {%8,%9}, {%0,%1,%2,%3};\n"
        : "+f"(c[0]), "+f"(c[1]), "+f"(c[2]), "+f"(c[3])
        : "r"(a[0]), "r"(a[1]), "r"(a[2]), "r"(a[3]), "r"(b0), "r"(b1));
}
__device__ __forceinline__ u32 saddr(const void* p)
{
    return (u32)__cvta_generic_to_shared(p);
}
__device__ __forceinline__ void cp16(u32 d, const void* s)
{
    asm volatile("cp.async.cg.shared.global [%0], [%1], 16;\n" :: "r"(d), "l"(s));
}
// SW128 swizzled byte offset: 16B chunk c (0..7) in a 128B row
__device__ __forceinline__ u32 sw16(int row, int c)
{
    return (u32)(row * 128 + (((c ^ row) & 7) << 4));
}
__device__ __forceinline__ float act_f(float v, int ACT)
{
    if (ACT == 1) return 1.f / (1.f + __expf(-v));
    if (ACT == 2) return tanhf(v);
    return v;
}

struct GArgs {
    const bf16* A; const bf16* B; const float* bias;
    float* Cf; bf16* Cs;
    int ldc, N, splitW, NST, ACT, EPI;
};

// split-store helper (EPI 1): write [hi|lo|hi] pair at row m, col n
__device__ __forceinline__ void split_store(bf16* Cs, int splitW, int m, int n,
                                            float v0, float v1)
{
    bf16 h0 = __float2bfloat16(v0);
    bf16 h1 = __float2bfloat16(v1);
    bf16 l0 = __float2bfloat16(v0 - __bfloat162float(h0));
    bf16 l1 = __float2bfloat16(v1 - __bfloat162float(h1));
    size_t b = (size_t)m * 3 * splitW;
    __nv_bfloat162 H; H.x = h0; H.y = h1;
    __nv_bfloat162 L; L.x = l0; L.y = l1;
    *reinterpret_cast<__nv_bfloat162*>(&Cs[b + n])              = H;
    *reinterpret_cast<__nv_bfloat162*>(&Cs[b + splitW + n])     = L;
    *reinterpret_cast<__nv_bfloat162*>(&Cs[b + 2 * splitW + n]) = H;
}

// ---------------------------------------------------------------------------
// 128x128 CTA tile core (verified round 12). occ 2.
// ---------------------------------------------------------------------------
__device__ __forceinline__ void mma_core128(const GArgs ga, int m0, int n0)
{
    extern __shared__ bf16 smbuf[];
    const int NST = ga.NST;
    const int KW  = NST * 64;

    const int tid  = threadIdx.x;
    const int lane = tid & 31, wid = tid >> 5;
    const int wm = wid & 1, wn = wid >> 1;

    float acc[4][4][4];
#pragma unroll
    for (int mt = 0; mt < 4; mt++)
#pragma unroll
        for (int nt = 0; nt < 4; nt++)
#pragma unroll
            for (int r = 0; r < 4; r++) acc[mt][nt][r] = 0.f;

    const bf16* Ag = ga.A + (size_t)m0 * KW;
    const bf16* Bg = ga.B + (size_t)n0 * KW;

    const int lr8 = (lane & 7) + ((lane >> 3) & 1) * 8;
    const int cq  = lane >> 4;

    const u32 ab0 = saddr(smbuf);
    const u32 bb0 = ab0 + 49152;

#define LOAD128(buf, k0)                                                   \
    do {                                                                   \
        u32 ab = ab0 + (buf) * 16384;                                      \
        u32 bb = bb0 + (buf) * 16384;                                      \
        _Pragma("unroll")                                                  \
        for (int i = 0; i < 4; i++) {                                      \
            int g = tid + i * 256;                                         \
            int row = g >> 3, c = g & 7;                                   \
            cp16(ab + sw16(row, c), Ag + (size_t)row * KW + (k0) + c * 8); \
            cp16(bb + sw16(row, c), Bg + (size_t)row * KW + (k0) + c * 8); \
        }                                                                  \
        asm volatile("cp.async.commit_group;\n");                          \
    } while (0)

    LOAD128(0, 0);
    LOAD128(1, 64);

    for (int st = 0; st < NST; st++) {
        if (st < NST - 1)
            asm volatile("cp.async.wait_group 1;\n");
        else
            asm volatile("cp.async.wait_group 0;\n");
        __syncthreads();
        if (st + 2 < NST)
            LOAD128((st + 2) % 3, (st + 2) * 64);

        const int buf = st % 3;
        const u32 ab = ab0 + buf * 16384;
        const u32 bb = bb0 + buf * 16384;
#pragma unroll
        for (int ks = 0; ks < 4; ks++) {
            const int chv = ks * 2 + cq;
            u32 af[4][4], bq[4][2];
#pragma unroll
            for (int mt = 0; mt < 4; mt++) {
                u32 ad = ab + sw16(wm * 64 + mt * 16 + lr8, chv);
                asm volatile(
                    "ldmatrix.sync.aligned.m8n8.x4.shared.b16 {%0,%1,%2,%3}, [%4];\n"
                    : "=r"(af[mt][0]), "=r"(af[mt][1]),
                      "=r"(af[mt][2]), "=r"(af[mt][3]) : "r"(ad));
            }
#pragma unroll
            for (int bh = 0; bh < 2; bh++) {
                u32 r0, r1, r2, r3;
                u32 ad = bb + sw16(wn * 32 + bh * 16 + lr8, chv);
                asm volatile(
                    "ldmatrix.sync.aligned.m8n8.x4.shared.b16 {%0,%1,%2,%3}, [%4];\n"
                    : "=r"(r0), "=r"(r1), "=r"(r2), "=r"(r3) : "r"(ad));
                bq[bh * 2 + 0][0] = r0; bq[bh * 2 + 0][1] = r2;
                bq[bh * 2 + 1][0] = r1; bq[bh * 2 + 1][1] = r3;
            }
#pragma unroll
            for (int mt = 0; mt < 4; mt++)
#pragma unroll
                for (int nt = 0; nt < 4; nt++)
                    mma16816(acc[mt][nt], af[mt], bq[nt][0], bq[nt][1]);
        }
    }
#undef LOAD128

    const int gidr = lane >> 2, tig = lane & 3;
#pragma unroll
    for (int nt = 0; nt < 4; nt++) {
        const int n = n0 + wn * 32 + nt * 8 + tig * 2;
        const bool ok0 = (n < ga.N), ok1 = (n + 1 < ga.N);
        const float bA = (ga.bias != nullptr && ok0) ? ga.bias[n] : 0.f;
        const float bB = (ga.bias != nullptr && ok1) ? ga.bias[n + 1] : 0.f;
#pragma unroll
        for (int mt = 0; mt < 4; mt++) {
            const int m = m0 + wm * 64 + mt * 16 + gidr;
            float v00 = act_f(acc[mt][nt][0] + bA, ga.ACT);
            float v01 = act_f(acc[mt][nt][1] + bB, ga.ACT);
            float v10 = act_f(acc[mt][nt][2] + bA, ga.ACT);
            float v11 = act_f(acc[mt][nt][3] + bB, ga.ACT);
            if (ga.EPI == 0) {
                if (ok0) {
                    ga.Cf[(size_t)m * ga.ldc + n]       = v00;
                    ga.Cf[(size_t)(m + 8) * ga.ldc + n] = v10;
                }
                if (ok1) {
                    ga.Cf[(size_t)m * ga.ldc + n + 1]       = v01;
                    ga.Cf[(size_t)(m + 8) * ga.ldc + n + 1] = v11;
                }
            } else if (ok1) {
                split_store(ga.Cs, ga.splitW, m,     n, v00, v01);
                split_store(ga.Cs, ga.splitW, m + 8, n, v10, v11);
            }
        }
    }
}

__global__ void __launch_bounds__(256, 2) mma_one(GArgs ga)
{
    mma_core128(ga, blockIdx.y * 128, blockIdx.x * 128);
}

__global__ void __launch_bounds__(256, 2) mma_fused3(GArgs a0, GArgs a1, GArgs a2)
{
    GArgs ga = (blockIdx.z == 0) ? a0 : (blockIdx.z == 1) ? a1 : a2;
    mma_core128(ga, blockIdx.y * 128, blockIdx.x * 128);
}

// ---------------------------------------------------------------------------
// Batched weight split: 8 small weights in one launch (B-side [hi|hi|lo]).
// grid (256, 8); slice z handles weight z, guard idx < NwPad*K.
// ---------------------------------------------------------------------------
struct WSplitArgs {
    const float* src[8];
    bf16*        dst[8];
    int Nw[8];      // valid rows
    int K[8];       // row width
    int total[8];   // NwPad * K elements
};

__global__ void convW_all_kernel(WSplitArgs wa)
{
    int z   = blockIdx.y;
    int idx = blockIdx.x * 256 + threadIdx.x;
    if (idx >= wa.total[z]) return;
    int K = wa.K[z];
    int r = idx / K, c = idx - r * K;
    float x = (r < wa.Nw[z]) ? wa.src[z][(size_t)r * K + c] : 0.f;
    bf16 h = __float2bfloat16(x);
    bf16 l = __float2bfloat16(x - __bfloat162float(h));
    bf16* Y = wa.dst[z];
    size_t base = (size_t)r * 3 * K;
    Y[base + c] = h; Y[base + K + c] = h; Y[base + 2 * K + c] = l;
}

// Wob split (big, separate launch)
__global__ void convW_kernel(const float* __restrict__ X, bf16* __restrict__ Y,
                             int Nw, int K)
{
    int idx = blockIdx.x * 256 + threadIdx.x;
    int r = idx / K, c = idx - r * K;
    float x = (r < Nw) ? X[(size_t)r * K + c] : 0.f;
    bf16 h = __float2bfloat16(x);
    bf16 l = __float2bfloat16(x - __bfloat162float(h));
    size_t base = (size_t)r * 3 * K;
    Y[base + c] = h; Y[base + K + c] = h; Y[base + 2 * K + c] = l;
}

// ---------------------------------------------------------------------------
// Gather -> qa3 [25600,768] and qe3 [25600,384], A-side split
// ---------------------------------------------------------------------------
__global__ void gather3_kernel(const int* __restrict__ q, const int* __restrict__ a,
                               const float* __restrict__ qet, const float* __restrict__ aet,
                               bf16* __restrict__ qa3, bf16* __restrict__ qe3)
{
    int tok = blockIdx.x;
    int i   = threadIdx.x;
    float v = (i < 128) ? qet[(size_t)q[tok] * 128 + i]
                        : aet[(size_t)a[tok] * 128 + (i - 128)];
    bf16 h = __float2bfloat16(v);
    bf16 l = __float2bfloat16(v - __bfloat162float(h));
    size_t b7 = (size_t)tok * 768;
    qa3[b7 + i] = h; qa3[b7 + 256 + i] = l; qa3[b7 + 512 + i] = h;
    if (i < 128) {
        size_t b3 = (size_t)tok * 384;
        qe3[b3 + i] = h; qe3[b3 + 128 + i] = l; qe3[b3 + 256 + i] = h;
    }
}

// ---------------------------------------------------------------------------
// qe-halves of beh3/mas3: pure copies from qa3 (split(h+l) == (h,l)).
// Independent of the scan; launched right after gather.
// ---------------------------------------------------------------------------
__global__ void qecopy3_kernel(const bf16* __restrict__ qa3,
                               bf16* __restrict__ beh3, bf16* __restrict__ mas3)
{
    int tok = blockIdx.x;          // 0..NTOK1-1
    int c   = threadIdx.x;         // 0..127
    int b   = tok / TM1;
    int t   = tok - b * TM1;
    size_t r0 = (size_t)(b * T_ + t) * 768;
    size_t r1 = r0 + 768;          // token t+1 of same batch
    bf16 h0 = qa3[r0 + c],  l0 = qa3[r0 + 256 + c];
    bf16 h1 = qa3[r1 + c],  l1 = qa3[r1 + 256 + c];
    size_t o = (size_t)tok * 768;
    beh3[o + 128 + c] = h0; beh3[o + 384 + c] = l0; beh3[o + 640 + c] = h0;
    mas3[o + 128 + c] = h1; mas3[o + 384 + c] = l1; mas3[o + 640 + c] = h1;
}

// ---------------------------------------------------------------------------
// softmax (verified)
// ---------------------------------------------------------------------------
__global__ void softmax64_kernel(const float* __restrict__ lg, float* __restrict__ co,
                                 int ntok)
{
    int g    = blockIdx.x * blockDim.x + threadIdx.x;
    int w    = g >> 5;
    int lane = g & 31;
    if (w >= ntok) return;
    const float* L = lg + (size_t)w * 64;
    float v0 = L[lane], v1 = L[lane + 32];
    float mx = fmaxf(v0, v1);
#pragma unroll
    for (int o = 16; o; o >>= 1) mx = fmaxf(mx, __shfl_xor_sync(0xffffffffu, mx, o));
    float e0 = __expf(v0 - mx), e1 = __expf(v1 - mx);
    float s = e0 + e1;
#pragma unroll
    for (int o = 16; o; o >>= 1) s += __shfl_xor_sync(0xffffffffu, s, o);
    float inv = 1.f / s;
    co[(size_t)w * 64 + lane]      = e0 * inv;
    co[(size_t)w * 64 + lane + 32] = e1 * inv;
}

// ---------------------------------------------------------------------------
// Sequential scan; epilogue writes rc/rcn DIRECTLY into beh3/mas3 in
// [hi|lo|hi] split form (cols 0..127 of each 256-section).
// ---------------------------------------------------------------------------
__global__ void __launch_bounds__(256) scan_kernel(
    const float* __restrict__ corr, const float* __restrict__ er,
    const float* __restrict__ ad,   const float* __restrict__ vinit,
    bf16* __restrict__ beh3, bf16* __restrict__ mas3)
{
    int b   = blockIdx.x;
    int tid = threadIdx.x;
    int v   = tid & 127;
    int cg  = tid >> 7;

    float M[32];
#pragma unroll
    for (int i = 0; i < 32; i++) M[i] = vinit[(size_t)(cg * 32 + i) * 128 + v];

    __shared__ float sw[64], swn[64], s_rc[128], s_rcn[128];

    const float* corr_b = corr + (size_t)b * T_ * 64;
    const float* er_b   = er   + (size_t)b * T_ * 128;
    const float* ad_b   = ad   + (size_t)b * T_ * 128;

    float ev_n = er_b[v];
    float av_n = ad_b[v];

    for (int t = 0; t < TM1; t++) {
        float ev = ev_n, av = av_n;
        if (t + 1 < TM1) {
            ev_n = er_b[(size_t)(t + 1) * 128 + v];
            av_n = ad_b[(size_t)(t + 1) * 128 + v];
        }
        if (tid < 64)       sw[tid]       = corr_b[(size_t)t * 64 + tid];
        else if (tid < 128) swn[tid - 64] = corr_b[(size_t)(t + 1) * 64 + (tid - 64)];
        __syncthreads();

        float prc = 0.f, prcn = 0.f;
#pragma unroll
        for (int i = 0; i < 32; i++) {
            float wc = sw[cg * 32 + i];
            float m  = fmaf(wc, av, M[i] * (1.f - wc * ev));
            M[i] = m;
            prc  = fmaf(wc, m, prc);
            prcn = fmaf(swn[cg * 32 + i], m, prcn);
        }
        if (cg == 0) { s_rc[v] = prc; s_rcn[v] = prcn; }
        __syncthreads();
        if (cg == 1) {
            float vb = s_rc[v]  + prc;
            float vm = s_rcn[v] + prcn;
            bf16 hb = __float2bfloat16(vb);
            bf16 lb = __float2bfloat16(vb - __bfloat162float(hb));
            bf16 hm = __float2bfloat16(vm);
            bf16 lm = __float2bfloat16(vm - __bfloat162float(hm));
            size_t o = (size_t)(b * TM1 + t) * 768;
            beh3[o + v] = hb; beh3[o + 256 + v] = lb; beh3[o + 512 + v] = hb;
            mas3[o + v] = hm; mas3[o + 256 + v] = lm; mas3[o + 512 + v] = hm;
        }
        __syncthreads();
    }
}

__global__ void pred_kernel(const float* __restrict__ hs, const float* __restrict__ Wo,
                            const float* __restrict__ bo, float* __restrict__ out, int ntok)
{
    int g    = blockIdx.x * blockDim.x + threadIdx.x;
    int w    = g >> 5;
    int lane = g & 31;
    if (w >= ntok) return;
    const float* h = hs + (size_t)w * 256;
    float s = 0.f;
#pragma unroll
    for (int j = 0; j < 8; j++) s = fmaf(h[lane + j * 32], Wo[lane + j * 32], s);
#pragma unroll
    for (int o = 16; o; o >>= 1) s += __shfl_xor_sync(0xffffffffu, s, o);
    if (lane == 0) out[w] = 1.f / (1.f + __expf(-(s + bo[0])));
}

// ---------------------------------------------------------------------------
// Launch
// ---------------------------------------------------------------------------
extern "C" void kernel_launch(void* const* d_in, const int* in_sizes, int n_in,
                              void* d_out, int out_size)
{
    (void)in_sizes; (void)n_in; (void)out_size;

    const int*   q_data     = (const int*)  d_in[0];
    const int*   a_data     = (const int*)  d_in[1];
    const float* q_embed    = (const float*)d_in[2];
    const float* a_embed    = (const float*)d_in[3];
    const float* key_matrix = (const float*)d_in[4];
    const float* value_init = (const float*)d_in[5];
    const float* Wk  = (const float*)d_in[6];   const float* bk  = (const float*)d_in[7];
    const float* We  = (const float*)d_in[8];   const float* be  = (const float*)d_in[9];
    const float* We2 = (const float*)d_in[10];  const float* be2 = (const float*)d_in[11];
    const float* Wa  = (const float*)d_in[12];  const float* ba  = (const float*)d_in[13];
    const float* Wa2 = (const float*)d_in[14];  const float* ba2 = (const float*)d_in[15];
    const float* Ws  = (const float*)d_in[16];  const float* bs  = (const float*)d_in[17];
    const float* Wo  = (const float*)d_in[18];  const float* bo  = (const float*)d_in[19];
    const float* Wsb = (const float*)d_in[20];  const float* bsb = (const float*)d_in[21];
    const float* Wob = (const float*)d_in[22];  const float* bob = (const float*)d_in[23];
    float* out = (float*)d_out;

    bf16 *p_qa3, *p_qe3, *p_t13, *p_t23, *p_rk3, *p_beh3, *p_mas3, *p_A3, *p_B3;
    bf16 *p_We3, *p_Wa3, *p_We23, *p_Wa23, *p_Wk3, *p_key3, *p_Wsb3, *p_Ws3;
    float *p_log, *p_corr, *p_er, *p_ad, *p_hs;
    cudaGetSymbolAddress((void**)&p_qa3,  g_qa3);
    cudaGetSymbolAddress((void**)&p_qe3,  g_qe3);
    cudaGetSymbolAddress((void**)&p_t13,  g_t13);
    cudaGetSymbolAddress((void**)&p_t23,  g_t23);
    cudaGetSymbolAddress((void**)&p_rk3,  g_rk3);
    cudaGetSymbolAddress((void**)&p_log,  g_logits);
    cudaGetSymbolAddress((void**)&p_corr, g_corr);
    cudaGetSymbolAddress((void**)&p_er,   g_erase);
    cudaGetSymbolAddress((void**)&p_ad,   g_add);
    cudaGetSymbolAddress((void**)&p_beh3, g_beh3);
    cudaGetSymbolAddress((void**)&p_mas3, g_mas3);
    cudaGetSymbolAddress((void**)&p_hs,   g_hs);
    cudaGetSymbolAddress((void**)&p_A3,   g_A3);
    cudaGetSymbolAddress((void**)&p_B3,   g_B3);
    cudaGetSymbolAddress((void**)&p_We3,  g_We3);
    cudaGetSymbolAddress((void**)&p_Wa3,  g_Wa3);
    cudaGetSymbolAddress((void**)&p_We23, g_We23);
    cudaGetSymbolAddress((void**)&p_Wa23, g_Wa23);
    cudaGetSymbolAddress((void**)&p_Wk3,  g_Wk3);
    cudaGetSymbolAddress((void**)&p_key3, g_key3);
    cudaGetSymbolAddress((void**)&p_Wsb3, g_Wsb3);
    cudaGetSymbolAddress((void**)&p_Ws3,  g_Ws3);

    cudaFuncSetAttribute(mma_one,    cudaFuncAttributeMaxDynamicSharedMemorySize, SMEM_128);
    cudaFuncSetAttribute(mma_fused3, cudaFuncAttributeMaxDynamicSharedMemorySize, SMEM_128);

    // ---- weight splits: 8 small in ONE launch + Wob separate ----
    {
        WSplitArgs wa;
        wa.src[0] = We;  wa.dst[0] = p_We3;  wa.Nw[0] = 128; wa.K[0] = 256; wa.total[0] = 128 * 256;
        wa.src[1] = Wa;  wa.dst[1] = p_Wa3;  wa.Nw[1] = 128; wa.K[1] = 256; wa.total[1] = 128 * 256;
        wa.src[2] = We2; wa.dst[2] = p_We23; wa.Nw[2] = 128; wa.K[2] = 128; wa.total[2] = 128 * 128;
        wa.src[3] = Wa2; wa.dst[3] = p_Wa23; wa.Nw[3] = 128; wa.K[3] = 128; wa.total[3] = 128 * 128;
        wa.src[4] = Wk;  wa.dst[4] = p_Wk3;  wa.Nw[4] = 128; wa.K[4] = 128; wa.total[4] = 128 * 128;
        wa.src[5] = key_matrix; wa.dst[5] = p_key3; wa.Nw[5] = 64; wa.K[5] = 128; wa.total[5] = 128 * 128;
        wa.src[6] = Wsb; wa.dst[6] = p_Wsb3; wa.Nw[6] = 256; wa.K[6] = 256; wa.total[6] = 256 * 256;
        wa.src[7] = Ws;  wa.dst[7] = p_Ws3;  wa.Nw[7] = 256; wa.K[7] = 256; wa.total[7] = 256 * 256;
        convW_all_kernel<<<dim3(256, 8), 256>>>(wa);
    }
    convW_kernel<<<NPAD * 256 / 256, 256>>>(Wob, p_B3, NQP1, 256);

    // ---- gather + qe-halves of beh3/mas3 (both independent of scan) ----
    gather3_kernel<<<NTOK, 256>>>(q_data, a_data, q_embed, a_embed, p_qa3, p_qe3);
    qecopy3_kernel<<<NTOK1, 128>>>(p_qa3, p_beh3, p_mas3);

    // ---- stage A: t1 | t2 | rk in one launch ----
    {
        GArgs a0 = { p_qa3, p_We3, be, nullptr, p_t13, 0, 128, 128, 12, 0, 1 };
        GArgs a1 = { p_qa3, p_Wa3, ba, nullptr, p_t23, 0, 128, 128, 12, 0, 1 };
        GArgs a2 = { p_qe3, p_Wk3, bk, nullptr, p_rk3, 0, 128, 128,  6, 0, 1 };
        mma_fused3<<<dim3(1, NTOK / 128, 3), 256, SMEM_128>>>(a0, a1, a2);
    }
    // ---- stage A: er | ad | logits in one launch ----
    {
        GArgs a0 = { p_t13, p_We23, be2, p_er,  nullptr, 128, 128, 0, 6, 1, 0 };
        GArgs a1 = { p_t23, p_Wa23, ba2, p_ad,  nullptr, 128, 128, 0, 6, 2, 0 };
        GArgs a2 = { p_rk3, p_key3, nullptr, p_log, nullptr, 64, 64, 0, 6, 0, 0 };
        mma_fused3<<<dim3(1, NTOK / 128, 3), 256, SMEM_128>>>(a0, a1, a2);
    }
    softmax64_kernel<<<(NTOK * 32 + 255) / 256, 256>>>(p_log, p_corr, NTOK);

    // ---- stage B: scan writes rc/rcn halves of beh3/mas3 directly ----
    scan_kernel<<<B_, 256>>>(p_corr, p_er, p_ad, value_init, p_beh3, p_mas3);

    // ---- stage C: wsb | ws (verified round-12 config) ----
    {
        GArgs a0 = { p_beh3, p_Wsb3, bsb, nullptr, p_A3, 0, 256, 256, 12, 2, 1 };
        GArgs a1 = { p_mas3, p_Ws3,  bs,  p_hs,  nullptr, 256, 256, 0, 12, 2, 0 };
        mma_fused3<<<dim3(2, NTOK1 / 128, 2), 256, SMEM_128>>>(a0, a1, a1);
    }
    pred_kernel<<<(NTOK1 * 32 + 255) / 256, 256>>>(p_hs, Wo, bo, out, NTOK1);

    // ---- big GEMM last (verified round-12 config) ----
    {
        GArgs ab = { p_A3, p_B3, bob, out + NTOK1, nullptr, NQP1, NQP1, 0, 12, 1, 0 };
        mma_one<<<dim3(NPAD / 128, NTOK1 / 128), 256, SMEM_128>>>(ab);
    }
}

// round 15
// speedup vs baseline: 1.7218x; 1.3168x over previous
#include <cuda_runtime.h>
#include <cuda_bf16.h>
#include <cuda_fp16.h>
#include <math.h>
#include <cstdint>

using u32 = unsigned int;
using u64 = unsigned long long;
typedef __nv_bfloat16 bf16;

// Problem constants
#define B_   128
#define T_   200
#define TM1  199
#define NQP1 5001
#define NPAD 5120
#define NTOK  (B_ * T_)    // 25600
#define NTOK1 (B_ * TM1)   // 25472

#define SMEM_128 98304     // 3-stage x (16KB A + 16KB B)

// ---------------------------------------------------------------------------
// Device scratch. bf16 split: A-side [hi|lo|hi], B-side [hi|hi|lo].
// Big GEMM operands are SINGLE fp16 (K=256): A2 [NTOK1][256], B2 [NPAD][256].
// ---------------------------------------------------------------------------
__device__ __align__(16) bf16  g_qa3  [(size_t)NTOK  * 768];
__device__ __align__(16) bf16  g_qe3  [(size_t)NTOK  * 384];
__device__ __align__(16) bf16  g_t13  [(size_t)NTOK  * 384];
__device__ __align__(16) bf16  g_t23  [(size_t)NTOK  * 384];
__device__ __align__(16) bf16  g_rk3  [(size_t)NTOK  * 384];
__device__ __align__(16) float g_logits[NTOK  *  64];
__device__ __align__(16) float g_corr  [NTOK  *  64];
__device__ __align__(16) float g_erase [NTOK  * 128];
__device__ __align__(16) float g_add   [NTOK  * 128];
__device__ __align__(16) bf16  g_beh3 [(size_t)NTOK1 * 768];
__device__ __align__(16) bf16  g_mas3 [(size_t)NTOK1 * 768];
__device__ __align__(16) float g_hs    [NTOK1 * 256];
__device__ __align__(16) __half g_A2  [(size_t)NTOK1 * 256];
__device__ __align__(16) __half g_B2  [(size_t)NPAD  * 256];
// split weights (B-side layout)
__device__ __align__(16) bf16  g_We3 [128 * 768];
__device__ __align__(16) bf16  g_Wa3 [128 * 768];
__device__ __align__(16) bf16  g_We23[128 * 384];
__device__ __align__(16) bf16  g_Wa23[128 * 384];
__device__ __align__(16) bf16  g_Wk3 [128 * 384];
__device__ __align__(16) bf16  g_key3[128 * 384];
__device__ __align__(16) bf16  g_Wsb3[256 * 768];
__device__ __align__(16) bf16  g_Ws3 [256 * 768];

// ---------------------------------------------------------------------------
// mma.sync helpers (bf16 core verified rounds 7-14; fp16 variant new)
// ---------------------------------------------------------------------------
__device__ __forceinline__ void mma_bf16(float c[4], const u32 a[4],
                                         u32 b0, u32 b1)
{
    asm volatile(
        "mma.sync.aligned.m16n8k16.row.col.f32.bf16.bf16.f32 "
        "{%0,%1,%2,%3}, {%4,%5,%6,%7}, {%8,%9}, {%0,%1,%2,%3};\n"
        : "+f"(c[0]), "+f"(c[1]), "+f"(c[2]), "+f"(c[3])
        : "r"(a[0]), "r"(a[1]), "r"(a[2]), "r"(a[3]), "r"(b0), "r"(b1));
}
__device__ __forceinline__ void mma_fp16(float c[4], const u32 a[4],
                                         u32 b0, u32 b1)
{
    asm volatile(
        "mma.sync.aligned.m16n8k16.row.col.f32.f16.f16.f32 "
        "{%0,%1,%2,%3}, {%4,%5,%6,%7}, {%8,%9}, {%0,%1,%2,%3};\n"
        : "+f"(c[0]), "+f"(c[1]), "+f"(c[2]), "+f"(c[3])
        : "r"(a[0]), "r"(a[1]), "r"(a[2]), "r"(a[3]), "r"(b0), "r"(b1));
}
__device__ __forceinline__ u32 saddr(const void* p)
{
    return (u32)__cvta_generic_to_shared(p);
}
__device__ __forceinline__ void cp16(u32 d, const void* s)
{
    asm volatile("cp.async.cg.shared.global [%0], [%1], 16;\n" :: "r"(d), "l"(s));
}
// SW128 swizzled byte offset: 16B chunk c (0..7) in a 128B row
__device__ __forceinline__ u32 sw16(int row, int c)
{
    return (u32)(row * 128 + (((c ^ row) & 7) << 4));
}
__device__ __forceinline__ float act_f(float v, int ACT)
{
    if (ACT == 1) return 1.f / (1.f + __expf(-v));
    if (ACT == 2) return tanhf(v);
    return v;
}

struct GArgs {
    const bf16* A; const bf16* B; const float* bias;
    float* Cf; bf16* Cs;
    int ldc, N, splitW, NST, ACT, EPI;
};

// split-store helper (EPI 1): write bf16 [hi|lo|hi] pair at row m, col n
__device__ __forceinline__ void split_store(bf16* Cs, int splitW, int m, int n,
                                            float v0, float v1)
{
    bf16 h0 = __float2bfloat16(v0);
    bf16 h1 = __float2bfloat16(v1);
    bf16 l0 = __float2bfloat16(v0 - __bfloat162float(h0));
    bf16 l1 = __float2bfloat16(v1 - __bfloat162float(h1));
    size_t b = (size_t)m * 3 * splitW;
    __nv_bfloat162 H; H.x = h0; H.y = h1;
    __nv_bfloat162 L; L.x = l0; L.y = l1;
    *reinterpret_cast<__nv_bfloat162*>(&Cs[b + n])              = H;
    *reinterpret_cast<__nv_bfloat162*>(&Cs[b + splitW + n])     = L;
    *reinterpret_cast<__nv_bfloat162*>(&Cs[b + 2 * splitW + n]) = H;
}

// ---------------------------------------------------------------------------
// 128x128 CTA tile core (structure verified round 12). occ 2.
// DT 0: bf16 mma.  DT 1: fp16 mma (identical 16-bit fragment handling).
// EPI 0: fp32 store. EPI 1: bf16 split store. EPI 2: plain fp16 store.
// ---------------------------------------------------------------------------
template<int DT>
__device__ __forceinline__ void mma_core128(const GArgs ga, int m0, int n0)
{
    extern __shared__ bf16 smbuf[];
    const int NST = ga.NST;
    const int KW  = NST * 64;

    const int tid  = threadIdx.x;
    const int lane = tid & 31, wid = tid >> 5;
    const int wm = wid & 1, wn = wid >> 1;

    float acc[4][4][4];
#pragma unroll
    for (int mt = 0; mt < 4; mt++)
#pragma unroll
        for (int nt = 0; nt < 4; nt++)
#pragma unroll
            for (int r = 0; r < 4; r++) acc[mt][nt][r] = 0.f;

    const bf16* Ag = ga.A + (size_t)m0 * KW;
    const bf16* Bg = ga.B + (size_t)n0 * KW;

    const int lr8 = (lane & 7) + ((lane >> 3) & 1) * 8;
    const int cq  = lane >> 4;

    const u32 ab0 = saddr(smbuf);
    const u32 bb0 = ab0 + 49152;

#define LOAD128(buf, k0)                                                   \
    do {                                                                   \
        u32 ab = ab0 + (buf) * 16384;                                      \
        u32 bb = bb0 + (buf) * 16384;                                      \
        _Pragma("unroll")                                                  \
        for (int i = 0; i < 4; i++) {                                      \
            int g = tid + i * 256;                                         \
            int row = g >> 3, c = g & 7;                                   \
            cp16(ab + sw16(row, c), Ag + (size_t)row * KW + (k0) + c * 8); \
            cp16(bb + sw16(row, c), Bg + (size_t)row * KW + (k0) + c * 8); \
        }                                                                  \
        asm volatile("cp.async.commit_group;\n");                          \
    } while (0)

    LOAD128(0, 0);
    LOAD128(1, 64);

    for (int st = 0; st < NST; st++) {
        if (st < NST - 1)
            asm volatile("cp.async.wait_group 1;\n");
        else
            asm volatile("cp.async.wait_group 0;\n");
        __syncthreads();
        if (st + 2 < NST)
            LOAD128((st + 2) % 3, (st + 2) * 64);

        const int buf = st % 3;
        const u32 ab = ab0 + buf * 16384;
        const u32 bb = bb0 + buf * 16384;
#pragma unroll
        for (int ks = 0; ks < 4; ks++) {
            const int chv = ks * 2 + cq;
            u32 af[4][4], bq[4][2];
#pragma unroll
            for (int mt = 0; mt < 4; mt++) {
                u32 ad = ab + sw16(wm * 64 + mt * 16 + lr8, chv);
                asm volatile(
                    "ldmatrix.sync.aligned.m8n8.x4.shared.b16 {%0,%1,%2,%3}, [%4];\n"
                    : "=r"(af[mt][0]), "=r"(af[mt][1]),
                      "=r"(af[mt][2]), "=r"(af[mt][3]) : "r"(ad));
            }
#pragma unroll
            for (int bh = 0; bh < 2; bh++) {
                u32 r0, r1, r2, r3;
                u32 ad = bb + sw16(wn * 32 + bh * 16 + lr8, chv);
                asm volatile(
                    "ldmatrix.sync.aligned.m8n8.x4.shared.b16 {%0,%1,%2,%3}, [%4];\n"
                    : "=r"(r0), "=r"(r1), "=r"(r2), "=r"(r3) : "r"(ad));
                bq[bh * 2 + 0][0] = r0; bq[bh * 2 + 0][1] = r2;
                bq[bh * 2 + 1][0] = r1; bq[bh * 2 + 1][1] = r3;
            }
#pragma unroll
            for (int mt = 0; mt < 4; mt++)
#pragma unroll
                for (int nt = 0; nt < 4; nt++) {
                    if (DT == 0)
                        mma_bf16(acc[mt][nt], af[mt], bq[nt][0], bq[nt][1]);
                    else
                        mma_fp16(acc[mt][nt], af[mt], bq[nt][0], bq[nt][1]);
                }
        }
    }
#undef LOAD128

    const int gidr = lane >> 2, tig = lane & 3;
#pragma unroll
    for (int nt = 0; nt < 4; nt++) {
        const int n = n0 + wn * 32 + nt * 8 + tig * 2;
        const bool ok0 = (n < ga.N), ok1 = (n + 1 < ga.N);
        const float bA = (ga.bias != nullptr && ok0) ? ga.bias[n] : 0.f;
        const float bB = (ga.bias != nullptr && ok1) ? ga.bias[n + 1] : 0.f;
#pragma unroll
        for (int mt = 0; mt < 4; mt++) {
            const int m = m0 + wm * 64 + mt * 16 + gidr;
            float v00 = act_f(acc[mt][nt][0] + bA, ga.ACT);
            float v01 = act_f(acc[mt][nt][1] + bB, ga.ACT);
            float v10 = act_f(acc[mt][nt][2] + bA, ga.ACT);
            float v11 = act_f(acc[mt][nt][3] + bB, ga.ACT);
            if (ga.EPI == 0) {
                if (ok0) {
                    ga.Cf[(size_t)m * ga.ldc + n]       = v00;
                    ga.Cf[(size_t)(m + 8) * ga.ldc + n] = v10;
                }
                if (ok1) {
                    ga.Cf[(size_t)m * ga.ldc + n + 1]       = v01;
                    ga.Cf[(size_t)(m + 8) * ga.ldc + n + 1] = v11;
                }
            } else if (ga.EPI == 1) {
                if (ok1) {
                    split_store(ga.Cs, ga.splitW, m,     n, v00, v01);
                    split_store(ga.Cs, ga.splitW, m + 8, n, v10, v11);
                }
            } else {   // EPI 2: plain fp16 store, row stride splitW
                if (ok1) {
                    __half* H = reinterpret_cast<__half*>(ga.Cs);
                    __half2 p0; p0.x = __float2half(v00); p0.y = __float2half(v01);
                    __half2 p1; p1.x = __float2half(v10); p1.y = __float2half(v11);
                    *reinterpret_cast<__half2*>(&H[(size_t)m * ga.splitW + n])       = p0;
                    *reinterpret_cast<__half2*>(&H[(size_t)(m + 8) * ga.splitW + n]) = p1;
                }
            }
        }
    }
}

__global__ void __launch_bounds__(256, 2) mma_one_f16(GArgs ga)
{
    mma_core128<1>(ga, blockIdx.y * 128, blockIdx.x * 128);
}

__global__ void __launch_bounds__(256, 2) mma_fused3(GArgs a0, GArgs a1, GArgs a2)
{
    GArgs ga = (blockIdx.z == 0) ? a0 : (blockIdx.z == 1) ? a1 : a2;
    mma_core128<0>(ga, blockIdx.y * 128, blockIdx.x * 128);
}

// ---------------------------------------------------------------------------
// Batched weight split (bf16 B-side [hi|hi|lo]); 8 small weights, one launch.
// ---------------------------------------------------------------------------
struct WSplitArgs {
    const float* src[8];
    bf16*        dst[8];
    int Nw[8];
    int K[8];
    int total[8];
};

__global__ void convW_all_kernel(WSplitArgs wa)
{
    int z   = blockIdx.y;
    int idx = blockIdx.x * 256 + threadIdx.x;
    if (idx >= wa.total[z]) return;
    int K = wa.K[z];
    int r = idx / K, c = idx - r * K;
    float x = (r < wa.Nw[z]) ? wa.src[z][(size_t)r * K + c] : 0.f;
    bf16 h = __float2bfloat16(x);
    bf16 l = __float2bfloat16(x - __bfloat162float(h));
    bf16* Y = wa.dst[z];
    size_t base = (size_t)r * 3 * K;
    Y[base + c] = h; Y[base + K + c] = h; Y[base + 2 * K + c] = l;
}

// Wob -> single fp16 [NPAD][256]; rows >= NQP1 zeroed
__global__ void convWob_f16(const float* __restrict__ X, __half* __restrict__ Y)
{
    int idx = blockIdx.x * 256 + threadIdx.x;   // < NPAD*256
    int r = idx >> 8, c = idx & 255;
    float x = (r < NQP1) ? X[(size_t)r * 256 + c] : 0.f;
    Y[(size_t)r * 256 + c] = __float2half(x);
}

// ---------------------------------------------------------------------------
// Gather -> qa3 [25600,768] and qe3 [25600,384], A-side split (verified)
// ---------------------------------------------------------------------------
__global__ void gather3_kernel(const int* __restrict__ q, const int* __restrict__ a,
                               const float* __restrict__ qet, const float* __restrict__ aet,
                               bf16* __restrict__ qa3, bf16* __restrict__ qe3)
{
    int tok = blockIdx.x;
    int i   = threadIdx.x;
    float v = (i < 128) ? qet[(size_t)q[tok] * 128 + i]
                        : aet[(size_t)a[tok] * 128 + (i - 128)];
    bf16 h = __float2bfloat16(v);
    bf16 l = __float2bfloat16(v - __bfloat162float(h));
    size_t b7 = (size_t)tok * 768;
    qa3[b7 + i] = h; qa3[b7 + 256 + i] = l; qa3[b7 + 512 + i] = h;
    if (i < 128) {
        size_t b3 = (size_t)tok * 384;
        qe3[b3 + i] = h; qe3[b3 + 128 + i] = l; qe3[b3 + 256 + i] = h;
    }
}

// qe-halves of beh3/mas3: pure copies from qa3 (verified round 14)
__global__ void qecopy3_kernel(const bf16* __restrict__ qa3,
                               bf16* __restrict__ beh3, bf16* __restrict__ mas3)
{
    int tok = blockIdx.x;
    int c   = threadIdx.x;
    int b   = tok / TM1;
    int t   = tok - b * TM1;
    size_t r0 = (size_t)(b * T_ + t) * 768;
    size_t r1 = r0 + 768;
    bf16 h0 = qa3[r0 + c],  l0 = qa3[r0 + 256 + c];
    bf16 h1 = qa3[r1 + c],  l1 = qa3[r1 + 256 + c];
    size_t o = (size_t)tok * 768;
    beh3[o + 128 + c] = h0; beh3[o + 384 + c] = l0; beh3[o + 640 + c] = h0;
    mas3[o + 128 + c] = h1; mas3[o + 384 + c] = l1; mas3[o + 640 + c] = h1;
}

// ---------------------------------------------------------------------------
// softmax (verified)
// ---------------------------------------------------------------------------
__global__ void softmax64_kernel(const float* __restrict__ lg, float* __restrict__ co,
                                 int ntok)
{
    int g    = blockIdx.x * blockDim.x + threadIdx.x;
    int w    = g >> 5;
    int lane = g & 31;
    if (w >= ntok) return;
    const float* L = lg + (size_t)w * 64;
    float v0 = L[lane], v1 = L[lane + 32];
    float mx = fmaxf(v0, v1);
#pragma unroll
    for (int o = 16; o; o >>= 1) mx = fmaxf(mx, __shfl_xor_sync(0xffffffffu, mx, o));
    float e0 = __expf(v0 - mx), e1 = __expf(v1 - mx);
    float s = e0 + e1;
#pragma unroll
    for (int o = 16; o; o >>= 1) s += __shfl_xor_sync(0xffffffffu, s, o);
    float inv = 1.f / s;
    co[(size_t)w * 64 + lane]      = e0 * inv;
    co[(size_t)w * 64 + lane + 32] = e1 * inv;
}

// ---------------------------------------------------------------------------
// Sequential scan; epilogue writes rc/rcn split directly (verified round 14)
// ---------------------------------------------------------------------------
__global__ void __launch_bounds__(256) scan_kernel(
    const float* __restrict__ corr, const float* __restrict__ er,
    const float* __restrict__ ad,   const float* __restrict__ vinit,
    bf16* __restrict__ beh3, bf16* __restrict__ mas3)
{
    int b   = blockIdx.x;
    int tid = threadIdx.x;
    int v   = tid & 127;
    int cg  = tid >> 7;

    float M[32];
#pragma unroll
    for (int i = 0; i < 32; i++) M[i] = vinit[(size_t)(cg * 32 + i) * 128 + v];

    __shared__ float sw[64], swn[64], s_rc[128], s_rcn[128];

    const float* corr_b = corr + (size_t)b * T_ * 64;
    const float* er_b   = er   + (size_t)b * T_ * 128;
    const float* ad_b   = ad   + (size_t)b * T_ * 128;

    float ev_n = er_b[v];
    float av_n = ad_b[v];

    for (int t = 0; t < TM1; t++) {
        float ev = ev_n, av = av_n;
        if (t + 1 < TM1) {
            ev_n = er_b[(size_t)(t + 1) * 128 + v];
            av_n = ad_b[(size_t)(t + 1) * 128 + v];
        }
        if (tid < 64)       sw[tid]       = corr_b[(size_t)t * 64 + tid];
        else if (tid < 128) swn[tid - 64] = corr_b[(size_t)(t + 1) * 64 + (tid - 64)];
        __syncthreads();

        float prc = 0.f, prcn = 0.f;
#pragma unroll
        for (int i = 0; i < 32; i++) {
            float wc = sw[cg * 32 + i];
            float m  = fmaf(wc, av, M[i] * (1.f - wc * ev));
            M[i] = m;
            prc  = fmaf(wc, m, prc);
            prcn = fmaf(swn[cg * 32 + i], m, prcn);
        }
        if (cg == 0) { s_rc[v] = prc; s_rcn[v] = prcn; }
        __syncthreads();
        if (cg == 1) {
            float vb = s_rc[v]  + prc;
            float vm = s_rcn[v] + prcn;
            bf16 hb = __float2bfloat16(vb);
            bf16 lb = __float2bfloat16(vb - __bfloat162float(hb));
            bf16 hm = __float2bfloat16(vm);
            bf16 lm = __float2bfloat16(vm - __bfloat162float(hm));
            size_t o = (size_t)(b * TM1 + t) * 768;
            beh3[o + v] = hb; beh3[o + 256 + v] = lb; beh3[o + 512 + v] = hb;
            mas3[o + v] = hm; mas3[o + 256 + v] = lm; mas3[o + 512 + v] = hm;
        }
        __syncthreads();
    }
}

__global__ void pred_kernel(const float* __restrict__ hs, const float* __restrict__ Wo,
                            const float* __restrict__ bo, float* __restrict__ out, int ntok)
{
    int g    = blockIdx.x * blockDim.x + threadIdx.x;
    int w    = g >> 5;
    int lane = g & 31;
    if (w >= ntok) return;
    const float* h = hs + (size_t)w * 256;
    float s = 0.f;
#pragma unroll
    for (int j = 0; j < 8; j++) s = fmaf(h[lane + j * 32], Wo[lane + j * 32], s);
#pragma unroll
    for (int o = 16; o; o >>= 1) s += __shfl_xor_sync(0xffffffffu, s, o);
    if (lane == 0) out[w] = 1.f / (1.f + __expf(-(s + bo[0])));
}

// ---------------------------------------------------------------------------
// Launch
// ---------------------------------------------------------------------------
extern "C" void kernel_launch(void* const* d_in, const int* in_sizes, int n_in,
                              void* d_out, int out_size)
{
    (void)in_sizes; (void)n_in; (void)out_size;

    const int*   q_data     = (const int*)  d_in[0];
    const int*   a_data     = (const int*)  d_in[1];
    const float* q_embed    = (const float*)d_in[2];
    const float* a_embed    = (const float*)d_in[3];
    const float* key_matrix = (const float*)d_in[4];
    const float* value_init = (const float*)d_in[5];
    const float* Wk  = (const float*)d_in[6];   const float* bk  = (const float*)d_in[7];
    const float* We  = (const float*)d_in[8];   const float* be  = (const float*)d_in[9];
    const float* We2 = (const float*)d_in[10];  const float* be2 = (const float*)d_in[11];
    const float* Wa  = (const float*)d_in[12];  const float* ba  = (const float*)d_in[13];
    const float* Wa2 = (const float*)d_in[14];  const float* ba2 = (const float*)d_in[15];
    const float* Ws  = (const float*)d_in[16];  const float* bs  = (const float*)d_in[17];
    const float* Wo  = (const float*)d_in[18];  const float* bo  = (const float*)d_in[19];
    const float* Wsb = (const float*)d_in[20];  const float* bsb = (const float*)d_in[21];
    const float* Wob = (const float*)d_in[22];  const float* bob = (const float*)d_in[23];
    float* out = (float*)d_out;

    bf16 *p_qa3, *p_qe3, *p_t13, *p_t23, *p_rk3, *p_beh3, *p_mas3;
    bf16 *p_We3, *p_Wa3, *p_We23, *p_Wa23, *p_Wk3, *p_key3, *p_Wsb3, *p_Ws3;
    __half *p_A2, *p_B2;
    float *p_log, *p_corr, *p_er, *p_ad, *p_hs;
    cudaGetSymbolAddress((void**)&p_qa3,  g_qa3);
    cudaGetSymbolAddress((void**)&p_qe3,  g_qe3);
    cudaGetSymbolAddress((void**)&p_t13,  g_t13);
    cudaGetSymbolAddress((void**)&p_t23,  g_t23);
    cudaGetSymbolAddress((void**)&p_rk3,  g_rk3);
    cudaGetSymbolAddress((void**)&p_log,  g_logits);
    cudaGetSymbolAddress((void**)&p_corr, g_corr);
    cudaGetSymbolAddress((void**)&p_er,   g_erase);
    cudaGetSymbolAddress((void**)&p_ad,   g_add);
    cudaGetSymbolAddress((void**)&p_beh3, g_beh3);
    cudaGetSymbolAddress((void**)&p_mas3, g_mas3);
    cudaGetSymbolAddress((void**)&p_hs,   g_hs);
    cudaGetSymbolAddress((void**)&p_A2,   g_A2);
    cudaGetSymbolAddress((void**)&p_B2,   g_B2);
    cudaGetSymbolAddress((void**)&p_We3,  g_We3);
    cudaGetSymbolAddress((void**)&p_Wa3,  g_Wa3);
    cudaGetSymbolAddress((void**)&p_We23, g_We23);
    cudaGetSymbolAddress((void**)&p_Wa23, g_Wa23);
    cudaGetSymbolAddress((void**)&p_Wk3,  g_Wk3);
    cudaGetSymbolAddress((void**)&p_key3, g_key3);
    cudaGetSymbolAddress((void**)&p_Wsb3, g_Wsb3);
    cudaGetSymbolAddress((void**)&p_Ws3,  g_Ws3);

    cudaFuncSetAttribute(mma_one_f16, cudaFuncAttributeMaxDynamicSharedMemorySize, SMEM_128);
    cudaFuncSetAttribute(mma_fused3,  cudaFuncAttributeMaxDynamicSharedMemorySize, SMEM_128);

    // ---- weight splits: 8 small in one launch + Wob fp16 separate ----
    {
        WSplitArgs wa;
        wa.src[0] = We;  wa.dst[0] = p_We3;  wa.Nw[0] = 128; wa.K[0] = 256; wa.total[0] = 128 * 256;
        wa.src[1] = Wa;  wa.dst[1] = p_Wa3;  wa.Nw[1] = 128; wa.K[1] = 256; wa.total[1] = 128 * 256;
        wa.src[2] = We2; wa.dst[2] = p_We23; wa.Nw[2] = 128; wa.K[2] = 128; wa.total[2] = 128 * 128;
        wa.src[3] = Wa2; wa.dst[3] = p_Wa23; wa.Nw[3] = 128; wa.K[3] = 128; wa.total[3] = 128 * 128;
        wa.src[4] = Wk;  wa.dst[4] = p_Wk3;  wa.Nw[4] = 128; wa.K[4] = 128; wa.total[4] = 128 * 128;
        wa.src[5] = key_matrix; wa.dst[5] = p_key3; wa.Nw[5] = 64; wa.K[5] = 128; wa.total[5] = 128 * 128;
        wa.src[6] = Wsb; wa.dst[6] = p_Wsb3; wa.Nw[6] = 256; wa.K[6] = 256; wa.total[6] = 256 * 256;
        wa.src[7] = Ws;  wa.dst[7] = p_Ws3;  wa.Nw[7] = 256; wa.K[7] = 256; wa.total[7] = 256 * 256;
        convW_all_kernel<<<dim3(256, 8), 256>>>(wa);
    }
    convWob_f16<<<NPAD * 256 / 256, 256>>>(Wob, p_B2);

    // ---- gather + qe-halves of beh3/mas3 ----
    gather3_kernel<<<NTOK, 256>>>(q_data, a_data, q_embed, a_embed, p_qa3, p_qe3);
    qecopy3_kernel<<<NTOK1, 128>>>(p_qa3, p_beh3, p_mas3);

    // ---- stage A: t1 | t2 | rk ----
    {
        GArgs a0 = { p_qa3, p_We3, be, nullptr, p_t13, 0, 128, 128, 12, 0, 1 };
        GArgs a1 = { p_qa3, p_Wa3, ba, nullptr, p_t23, 0, 128, 128, 12, 0, 1 };
        GArgs a2 = { p_qe3, p_Wk3, bk, nullptr, p_rk3, 0, 128, 128,  6, 0, 1 };
        mma_fused3<<<dim3(1, NTOK / 128, 3), 256, SMEM_128>>>(a0, a1, a2);
    }
    // ---- stage A: er | ad | logits ----
    {
        GArgs a0 = { p_t13, p_We23, be2, p_er,  nullptr, 128, 128, 0, 6, 1, 0 };
        GArgs a1 = { p_t23, p_Wa23, ba2, p_ad,  nullptr, 128, 128, 0, 6, 2, 0 };
        GArgs a2 = { p_rk3, p_key3, nullptr, p_log, nullptr, 64, 64, 0, 6, 0, 0 };
        mma_fused3<<<dim3(1, NTOK / 128, 3), 256, SMEM_128>>>(a0, a1, a2);
    }
    softmax64_kernel<<<(NTOK * 32 + 255) / 256, 256>>>(p_log, p_corr, NTOK);

    // ---- stage B: scan writes rc/rcn halves directly ----
    scan_kernel<<<B_, 256>>>(p_corr, p_er, p_ad, value_init, p_beh3, p_mas3);

    // ---- stage C: wsb (fp16 epilogue -> A2) | ws (fp32 -> hs) ----
    {
        GArgs a0 = { p_beh3, p_Wsb3, bsb, nullptr, (bf16*)p_A2, 0, 256, 256, 12, 2, 2 };
        GArgs a1 = { p_mas3, p_Ws3,  bs,  p_hs,  nullptr,       256, 256, 0, 12, 2, 0 };
        mma_fused3<<<dim3(2, NTOK1 / 128, 2), 256, SMEM_128>>>(a0, a1, a1);
    }
    pred_kernel<<<(NTOK1 * 32 + 255) / 256, 256>>>(p_hs, Wo, bo, out, NTOK1);

    // ---- big GEMM last: single-fp16, K=256 (NST=4) ----
    {
        GArgs ab = { (const bf16*)p_A2, (const bf16*)p_B2, bob, out + NTOK1,
                     nullptr, NQP1, NQP1, 0, 4, 1, 0 };
        mma_one_f16<<<dim3(NPAD / 128, NTOK1 / 128), 256, SMEM_128>>>(ab);
    }
}

// round 16
// speedup vs baseline: 1.9111x; 1.1100x over previous
#include <cuda_runtime.h>
#include <cuda_fp16.h>
#include <math.h>
#include <cstdint>

using u32 = unsigned int;
using u64 = unsigned long long;

// Problem constants
#define B_   128
#define T_   200
#define TM1  199
#define NQP1 5001
#define NPAD 5120
#define NTOK  (B_ * T_)    // 25600
#define NTOK1 (B_ * TM1)   // 25472

#define SMEM_128 98304     // 3-stage x (16KB A + 16KB B)

// ---------------------------------------------------------------------------
// Device scratch — ALL GEMM operands plain fp16 [rows, K].
// ---------------------------------------------------------------------------
__device__ __align__(16) __half g_qa2 [(size_t)NTOK  * 256];  // [qe | ae]
__device__ __align__(16) __half g_t12 [(size_t)NTOK  * 128];
__device__ __align__(16) __half g_t22 [(size_t)NTOK  * 128];
__device__ __align__(16) __half g_rk2 [(size_t)NTOK  * 128];
__device__ __align__(16) float g_logits[NTOK  *  64];
__device__ __align__(16) float g_corr  [NTOK  *  64];
__device__ __align__(16) float g_erase [NTOK  * 128];
__device__ __align__(16) float g_add   [NTOK  * 128];
__device__ __align__(16) __half g_beh2[(size_t)NTOK1 * 256];  // [rc | qe_t]
__device__ __align__(16) __half g_mas2[(size_t)NTOK1 * 256];  // [rcn | qe_t1]
__device__ __align__(16) float g_hs    [NTOK1 * 256];
__device__ __align__(16) __half g_A2  [(size_t)NTOK1 * 256];  // tanh(beh@Wsb)
__device__ __align__(16) __half g_B2  [(size_t)NPAD  * 256];  // Wob
// fp16 weights (plain [Npad, K])
__device__ __align__(16) __half g_We2 [128 * 256];
__device__ __align__(16) __half g_Wa2 [128 * 256];
__device__ __align__(16) __half g_We22[128 * 128];
__device__ __align__(16) __half g_Wa22[128 * 128];
__device__ __align__(16) __half g_Wk2 [128 * 128];
__device__ __align__(16) __half g_key2[128 * 128];  // 64 valid rows, rest 0
__device__ __align__(16) __half g_Wsb2[256 * 256];
__device__ __align__(16) __half g_Ws2 [256 * 256];

// ---------------------------------------------------------------------------
// mma helpers (fragment machinery verified rounds 7-15)
// ---------------------------------------------------------------------------
__device__ __forceinline__ void mma_fp16(float c[4], const u32 a[4],
                                         u32 b0, u32 b1)
{
    asm volatile(
        "mma.sync.aligned.m16n8k16.row.col.f32.f16.f16.f32 "
        "{%0,%1,%2,%3}, {%4,%5,%6,%7}, {%8,%9}, {%0,%1,%2,%3};\n"
        : "+f"(c[0]), "+f"(c[1]), "+f"(c[2]), "+f"(c[3])
        : "r"(a[0]), "r"(a[1]), "r"(a[2]), "r"(a[3]), "r"(b0), "r"(b1));
}
__device__ __forceinline__ u32 saddr(const void* p)
{
    return (u32)__cvta_generic_to_shared(p);
}
__device__ __forceinline__ void cp16(u32 d, const void* s)
{
    asm volatile("cp.async.cg.shared.global [%0], [%1], 16;\n" :: "r"(d), "l"(s));
}
// SW128 swizzled byte offset: 16B chunk c (0..7) in a 128B row
__device__ __forceinline__ u32 sw16(int row, int c)
{
    return (u32)(row * 128 + (((c ^ row) & 7) << 4));
}
__device__ __forceinline__ float act_f(float v, int ACT)
{
    if (ACT == 1) return 1.f / (1.f + __expf(-v));
    if (ACT == 2) return tanhf(v);
    return v;
}

struct GArgs {
    const __half* A;      // [M, lda], K-major
    const __half* B;      // [Npad, NST*64]
    const float* bias;    // [N] or null
    float*  Cf;           // EPI 0 target
    __half* Ch;           // EPI 2 target
    int lda, ldc, N, NST, ACT, EPI;
};

// ---------------------------------------------------------------------------
// 128x128 CTA tile fp16 core. occ 2, 3-stage cp.async, K-chunk 64.
// EPI 0: fp32 store (ldc). EPI 2: fp16 store (ldc).
// ---------------------------------------------------------------------------
__device__ __forceinline__ void mma_core_f16(const GArgs ga, int m0, int n0)
{
    extern __shared__ __half smbuf[];
    const int NST = ga.NST;
    const int KW  = NST * 64;

    const int tid  = threadIdx.x;
    const int lane = tid & 31, wid = tid >> 5;
    const int wm = wid & 1, wn = wid >> 1;

    float acc[4][4][4];
#pragma unroll
    for (int mt = 0; mt < 4; mt++)
#pragma unroll
        for (int nt = 0; nt < 4; nt++)
#pragma unroll
            for (int r = 0; r < 4; r++) acc[mt][nt][r] = 0.f;

    const __half* Ag = ga.A + (size_t)m0 * ga.lda;
    const __half* Bg = ga.B + (size_t)n0 * KW;

    const int lr8 = (lane & 7) + ((lane >> 3) & 1) * 8;
    const int cq  = lane >> 4;

    const u32 ab0 = saddr(smbuf);
    const u32 bb0 = ab0 + 49152;

#define LOAD128(buf, k0)                                                       \
    do {                                                                       \
        u32 ab = ab0 + (buf) * 16384;                                          \
        u32 bb = bb0 + (buf) * 16384;                                          \
        _Pragma("unroll")                                                      \
        for (int i = 0; i < 4; i++) {                                          \
            int g = tid + i * 256;                                             \
            int row = g >> 3, c = g & 7;                                       \
            cp16(ab + sw16(row, c), Ag + (size_t)row * ga.lda + (k0) + c * 8); \
            cp16(bb + sw16(row, c), Bg + (size_t)row * KW + (k0) + c * 8);     \
        }                                                                      \
        asm volatile("cp.async.commit_group;\n");                              \
    } while (0)

    LOAD128(0, 0);
    LOAD128(1, 64);

    for (int st = 0; st < NST; st++) {
        if (st < NST - 1)
            asm volatile("cp.async.wait_group 1;\n");
        else
            asm volatile("cp.async.wait_group 0;\n");
        __syncthreads();
        if (st + 2 < NST)
            LOAD128((st + 2) % 3, (st + 2) * 64);

        const int buf = st % 3;
        const u32 ab = ab0 + buf * 16384;
        const u32 bb = bb0 + buf * 16384;
#pragma unroll
        for (int ks = 0; ks < 4; ks++) {
            const int chv = ks * 2 + cq;
            u32 af[4][4], bq[4][2];
#pragma unroll
            for (int mt = 0; mt < 4; mt++) {
                u32 ad = ab + sw16(wm * 64 + mt * 16 + lr8, chv);
                asm volatile(
                    "ldmatrix.sync.aligned.m8n8.x4.shared.b16 {%0,%1,%2,%3}, [%4];\n"
                    : "=r"(af[mt][0]), "=r"(af[mt][1]),
                      "=r"(af[mt][2]), "=r"(af[mt][3]) : "r"(ad));
            }
#pragma unroll
            for (int bh = 0; bh < 2; bh++) {
                u32 r0, r1, r2, r3;
                u32 ad = bb + sw16(wn * 32 + bh * 16 + lr8, chv);
                asm volatile(
                    "ldmatrix.sync.aligned.m8n8.x4.shared.b16 {%0,%1,%2,%3}, [%4];\n"
                    : "=r"(r0), "=r"(r1), "=r"(r2), "=r"(r3) : "r"(ad));
                bq[bh * 2 + 0][0] = r0; bq[bh * 2 + 0][1] = r2;
                bq[bh * 2 + 1][0] = r1; bq[bh * 2 + 1][1] = r3;
            }
#pragma unroll
            for (int mt = 0; mt < 4; mt++)
#pragma unroll
                for (int nt = 0; nt < 4; nt++)
                    mma_fp16(acc[mt][nt], af[mt], bq[nt][0], bq[nt][1]);
        }
    }
#undef LOAD128

    const int gidr = lane >> 2, tig = lane & 3;
#pragma unroll
    for (int nt = 0; nt < 4; nt++) {
        const int n = n0 + wn * 32 + nt * 8 + tig * 2;
        const bool ok0 = (n < ga.N), ok1 = (n + 1 < ga.N);
        const float bA = (ga.bias != nullptr && ok0) ? ga.bias[n] : 0.f;
        const float bB = (ga.bias != nullptr && ok1) ? ga.bias[n + 1] : 0.f;
#pragma unroll
        for (int mt = 0; mt < 4; mt++) {
            const int m = m0 + wm * 64 + mt * 16 + gidr;
            float v00 = act_f(acc[mt][nt][0] + bA, ga.ACT);
            float v01 = act_f(acc[mt][nt][1] + bB, ga.ACT);
            float v10 = act_f(acc[mt][nt][2] + bA, ga.ACT);
            float v11 = act_f(acc[mt][nt][3] + bB, ga.ACT);
            if (ga.EPI == 0) {
                if (ok0) {
                    ga.Cf[(size_t)m * ga.ldc + n]       = v00;
                    ga.Cf[(size_t)(m + 8) * ga.ldc + n] = v10;
                }
                if (ok1) {
                    ga.Cf[(size_t)m * ga.ldc + n + 1]       = v01;
                    ga.Cf[(size_t)(m + 8) * ga.ldc + n + 1] = v11;
                }
            } else {   // EPI 2: fp16 pair store
                if (ok1) {
                    __half2 p0; p0.x = __float2half(v00); p0.y = __float2half(v01);
                    __half2 p1; p1.x = __float2half(v10); p1.y = __float2half(v11);
                    *reinterpret_cast<__half2*>(&ga.Ch[(size_t)m * ga.ldc + n])       = p0;
                    *reinterpret_cast<__half2*>(&ga.Ch[(size_t)(m + 8) * ga.ldc + n]) = p1;
                }
            }
        }
    }
}

__global__ void __launch_bounds__(256, 2) mma_one(GArgs ga)
{
    mma_core_f16(ga, blockIdx.y * 128, blockIdx.x * 128);
}

__global__ void __launch_bounds__(256, 2) mma_fused3(GArgs a0, GArgs a1, GArgs a2)
{
    GArgs ga = (blockIdx.z == 0) ? a0 : (blockIdx.z == 1) ? a1 : a2;
    mma_core_f16(ga, blockIdx.y * 128, blockIdx.x * 128);
}

// ---------------------------------------------------------------------------
// Batched weight conversion to fp16 (8 small weights, one launch)
// ---------------------------------------------------------------------------
struct WConvArgs {
    const float* src[8];
    __half*      dst[8];
    int Nw[8];      // valid rows (rest zeroed)
    int K[8];
    int total[8];   // NwPad * K
};

__global__ void convW_all_kernel(WConvArgs wa)
{
    int z   = blockIdx.y;
    int idx = blockIdx.x * 256 + threadIdx.x;
    if (idx >= wa.total[z]) return;
    int K = wa.K[z];
    int r = idx / K, c = idx - r * K;
    float x = (r < wa.Nw[z]) ? wa.src[z][(size_t)r * K + c] : 0.f;
    wa.dst[z][(size_t)r * K + c] = __float2half(x);
}

// Wob -> fp16 [NPAD][256]
__global__ void convWob_f16(const float* __restrict__ X, __half* __restrict__ Y)
{
    int idx = blockIdx.x * 256 + threadIdx.x;
    int r = idx >> 8, c = idx & 255;
    float x = (r < NQP1) ? X[(size_t)r * 256 + c] : 0.f;
    Y[(size_t)r * 256 + c] = __float2half(x);
}

// ---------------------------------------------------------------------------
// Gather -> qa2 [NTOK,256] fp16 (qe = cols 0..127, ae = cols 128..255)
// ---------------------------------------------------------------------------
__global__ void gather2_kernel(const int* __restrict__ q, const int* __restrict__ a,
                               const float* __restrict__ qet, const float* __restrict__ aet,
                               __half* __restrict__ qa2)
{
    int tok = blockIdx.x;
    int i   = threadIdx.x;
    float v = (i < 128) ? qet[(size_t)q[tok] * 128 + i]
                        : aet[(size_t)a[tok] * 128 + (i - 128)];
    qa2[(size_t)tok * 256 + i] = __float2half(v);
}

// qe-halves of beh2/mas2: plain copies from qa2
__global__ void qecopy2_kernel(const __half* __restrict__ qa2,
                               __half* __restrict__ beh2, __half* __restrict__ mas2)
{
    int tok = blockIdx.x;          // 0..NTOK1-1
    int c   = threadIdx.x;         // 0..127
    int b   = tok / TM1;
    int t   = tok - b * TM1;
    size_t r0 = (size_t)(b * T_ + t) * 256;
    size_t o  = (size_t)tok * 256;
    beh2[o + 128 + c] = qa2[r0 + c];
    mas2[o + 128 + c] = qa2[r0 + 256 + c];   // token t+1 qe
}

// ---------------------------------------------------------------------------
// softmax (verified)
// ---------------------------------------------------------------------------
__global__ void softmax64_kernel(const float* __restrict__ lg, float* __restrict__ co,
                                 int ntok)
{
    int g    = blockIdx.x * blockDim.x + threadIdx.x;
    int w    = g >> 5;
    int lane = g & 31;
    if (w >= ntok) return;
    const float* L = lg + (size_t)w * 64;
    float v0 = L[lane], v1 = L[lane + 32];
    float mx = fmaxf(v0, v1);
#pragma unroll
    for (int o = 16; o; o >>= 1) mx = fmaxf(mx, __shfl_xor_sync(0xffffffffu, mx, o));
    float e0 = __expf(v0 - mx), e1 = __expf(v1 - mx);
    float s = e0 + e1;
#pragma unroll
    for (int o = 16; o; o >>= 1) s += __shfl_xor_sync(0xffffffffu, s, o);
    float inv = 1.f / s;
    co[(size_t)w * 64 + lane]      = e0 * inv;
    co[(size_t)w * 64 + lane + 32] = e1 * inv;
}

// ---------------------------------------------------------------------------
// Sequential scan (fp32 internal); writes rc/rcn as fp16 into beh2/mas2
// ---------------------------------------------------------------------------
__global__ void __launch_bounds__(256) scan_kernel(
    const float* __restrict__ corr, const float* __restrict__ er,
    const float* __restrict__ ad,   const float* __restrict__ vinit,
    __half* __restrict__ beh2, __half* __restrict__ mas2)
{
    int b   = blockIdx.x;
    int tid = threadIdx.x;
    int v   = tid & 127;
    int cg  = tid >> 7;

    float M[32];
#pragma unroll
    for (int i = 0; i < 32; i++) M[i] = vinit[(size_t)(cg * 32 + i) * 128 + v];

    __shared__ float sw[64], swn[64], s_rc[128], s_rcn[128];

    const float* corr_b = corr + (size_t)b * T_ * 64;
    const float* er_b   = er   + (size_t)b * T_ * 128;
    const float* ad_b   = ad   + (size_t)b * T_ * 128;

    float ev_n = er_b[v];
    float av_n = ad_b[v];

    for (int t = 0; t < TM1; t++) {
        float ev = ev_n, av = av_n;
        if (t + 1 < TM1) {
            ev_n = er_b[(size_t)(t + 1) * 128 + v];
            av_n = ad_b[(size_t)(t + 1) * 128 + v];
        }
        if (tid < 64)       sw[tid]       = corr_b[(size_t)t * 64 + tid];
        else if (tid < 128) swn[tid - 64] = corr_b[(size_t)(t + 1) * 64 + (tid - 64)];
        __syncthreads();

        float prc = 0.f, prcn = 0.f;
#pragma unroll
        for (int i = 0; i < 32; i++) {
            float wc = sw[cg * 32 + i];
            float m  = fmaf(wc, av, M[i] * (1.f - wc * ev));
            M[i] = m;
            prc  = fmaf(wc, m, prc);
            prcn = fmaf(swn[cg * 32 + i], m, prcn);
        }
        if (cg == 0) { s_rc[v] = prc; s_rcn[v] = prcn; }
        __syncthreads();
        if (cg == 1) {
            float vb = s_rc[v]  + prc;
            float vm = s_rcn[v] + prcn;
            size_t o = (size_t)(b * TM1 + t) * 256;
            beh2[o + v] = __float2half(vb);
            mas2[o + v] = __float2half(vm);
        }
        __syncthreads();
    }
}

__global__ void pred_kernel(const float* __restrict__ hs, const float* __restrict__ Wo,
                            const float* __restrict__ bo, float* __restrict__ out, int ntok)
{
    int g    = blockIdx.x * blockDim.x + threadIdx.x;
    int w    = g >> 5;
    int lane = g & 31;
    if (w >= ntok) return;
    const float* h = hs + (size_t)w * 256;
    float s = 0.f;
#pragma unroll
    for (int j = 0; j < 8; j++) s = fmaf(h[lane + j * 32], Wo[lane + j * 32], s);
#pragma unroll
    for (int o = 16; o; o >>= 1) s += __shfl_xor_sync(0xffffffffu, s, o);
    if (lane == 0) out[w] = 1.f / (1.f + __expf(-(s + bo[0])));
}

// ---------------------------------------------------------------------------
// Launch
// ---------------------------------------------------------------------------
extern "C" void kernel_launch(void* const* d_in, const int* in_sizes, int n_in,
                              void* d_out, int out_size)
{
    (void)in_sizes; (void)n_in; (void)out_size;

    const int*   q_data     = (const int*)  d_in[0];
    const int*   a_data     = (const int*)  d_in[1];
    const float* q_embed    = (const float*)d_in[2];
    const float* a_embed    = (const float*)d_in[3];
    const float* key_matrix = (const float*)d_in[4];
    const float* value_init = (const float*)d_in[5];
    const float* Wk  = (const float*)d_in[6];   const float* bk  = (const float*)d_in[7];
    const float* We  = (const float*)d_in[8];   const float* be  = (const float*)d_in[9];
    const float* We2 = (const float*)d_in[10];  const float* be2 = (const float*)d_in[11];
    const float* Wa  = (const float*)d_in[12];  const float* ba  = (const float*)d_in[13];
    const float* Wa2 = (const float*)d_in[14];  const float* ba2 = (const float*)d_in[15];
    const float* Ws  = (const float*)d_in[16];  const float* bs  = (const float*)d_in[17];
    const float* Wo  = (const float*)d_in[18];  const float* bo  = (const float*)d_in[19];
    const float* Wsb = (const float*)d_in[20];  const float* bsb = (const float*)d_in[21];
    const float* Wob = (const float*)d_in[22];  const float* bob = (const float*)d_in[23];
    float* out = (float*)d_out;

    __half *p_qa2, *p_t12, *p_t22, *p_rk2, *p_beh2, *p_mas2, *p_A2, *p_B2;
    __half *p_We2, *p_Wa2, *p_We22, *p_Wa22, *p_Wk2, *p_key2, *p_Wsb2, *p_Ws2;
    float *p_log, *p_corr, *p_er, *p_ad, *p_hs;
    cudaGetSymbolAddress((void**)&p_qa2,  g_qa2);
    cudaGetSymbolAddress((void**)&p_t12,  g_t12);
    cudaGetSymbolAddress((void**)&p_t22,  g_t22);
    cudaGetSymbolAddress((void**)&p_rk2,  g_rk2);
    cudaGetSymbolAddress((void**)&p_log,  g_logits);
    cudaGetSymbolAddress((void**)&p_corr, g_corr);
    cudaGetSymbolAddress((void**)&p_er,   g_erase);
    cudaGetSymbolAddress((void**)&p_ad,   g_add);
    cudaGetSymbolAddress((void**)&p_beh2, g_beh2);
    cudaGetSymbolAddress((void**)&p_mas2, g_mas2);
    cudaGetSymbolAddress((void**)&p_hs,   g_hs);
    cudaGetSymbolAddress((void**)&p_A2,   g_A2);
    cudaGetSymbolAddress((void**)&p_B2,   g_B2);
    cudaGetSymbolAddress((void**)&p_We2,  g_We2);
    cudaGetSymbolAddress((void**)&p_Wa2,  g_Wa2);
    cudaGetSymbolAddress((void**)&p_We22, g_We22);
    cudaGetSymbolAddress((void**)&p_Wa22, g_Wa22);
    cudaGetSymbolAddress((void**)&p_Wk2,  g_Wk2);
    cudaGetSymbolAddress((void**)&p_key2, g_key2);
    cudaGetSymbolAddress((void**)&p_Wsb2, g_Wsb2);
    cudaGetSymbolAddress((void**)&p_Ws2,  g_Ws2);

    cudaFuncSetAttribute(mma_one,    cudaFuncAttributeMaxDynamicSharedMemorySize, SMEM_128);
    cudaFuncSetAttribute(mma_fused3, cudaFuncAttributeMaxDynamicSharedMemorySize, SMEM_128);

    // ---- weight conversions ----
    {
        WConvArgs wa;
        wa.src[0] = We;  wa.dst[0] = p_We2;  wa.Nw[0] = 128; wa.K[0] = 256; wa.total[0] = 128 * 256;
        wa.src[1] = Wa;  wa.dst[1] = p_Wa2;  wa.Nw[1] = 128; wa.K[1] = 256; wa.total[1] = 128 * 256;
        wa.src[2] = We2; wa.dst[2] = p_We22; wa.Nw[2] = 128; wa.K[2] = 128; wa.total[2] = 128 * 128;
        wa.src[3] = Wa2; wa.dst[3] = p_Wa22; wa.Nw[3] = 128; wa.K[3] = 128; wa.total[3] = 128 * 128;
        wa.src[4] = Wk;  wa.dst[4] = p_Wk2;  wa.Nw[4] = 128; wa.K[4] = 128; wa.total[4] = 128 * 128;
        wa.src[5] = key_matrix; wa.dst[5] = p_key2; wa.Nw[5] = 64; wa.K[5] = 128; wa.total[5] = 128 * 128;
        wa.src[6] = Wsb; wa.dst[6] = p_Wsb2; wa.Nw[6] = 256; wa.K[6] = 256; wa.total[6] = 256 * 256;
        wa.src[7] = Ws;  wa.dst[7] = p_Ws2;  wa.Nw[7] = 256; wa.K[7] = 256; wa.total[7] = 256 * 256;
        convW_all_kernel<<<dim3(256, 8), 256>>>(wa);
    }
    convWob_f16<<<NPAD * 256 / 256, 256>>>(Wob, p_B2);

    // ---- gather + qe-halves of beh2/mas2 ----
    gather2_kernel<<<NTOK, 256>>>(q_data, a_data, q_embed, a_embed, p_qa2);
    qecopy2_kernel<<<NTOK1, 128>>>(p_qa2, p_beh2, p_mas2);

    // ---- stage A: t1 | t2 | rk (all fp16, K=256/256/128) ----
    {
        GArgs a0 = { p_qa2, p_We2, be, nullptr, p_t12, 256, 128, 128, 4, 0, 2 };
        GArgs a1 = { p_qa2, p_Wa2, ba, nullptr, p_t22, 256, 128, 128, 4, 0, 2 };
        GArgs a2 = { p_qa2, p_Wk2, bk, nullptr, p_rk2, 256, 128, 128, 2, 0, 2 };
        mma_fused3<<<dim3(1, NTOK / 128, 3), 256, SMEM_128>>>(a0, a1, a2);
    }
    // ---- stage A: er | ad | logits (K=128) ----
    {
        GArgs a0 = { p_t12, p_We22, be2, p_er,  nullptr, 128, 128, 128, 2, 1, 0 };
        GArgs a1 = { p_t22, p_Wa22, ba2, p_ad,  nullptr, 128, 128, 128, 2, 2, 0 };
        GArgs a2 = { p_rk2, p_key2, nullptr, p_log, nullptr, 128, 64, 64, 2, 0, 0 };
        mma_fused3<<<dim3(1, NTOK / 128, 3), 256, SMEM_128>>>(a0, a1, a2);
    }
    softmax64_kernel<<<(NTOK * 32 + 255) / 256, 256>>>(p_log, p_corr, NTOK);

    // ---- stage B: scan writes rc/rcn halves of beh2/mas2 ----
    scan_kernel<<<B_, 256>>>(p_corr, p_er, p_ad, value_init, p_beh2, p_mas2);

    // ---- stage C: wsb (fp16 -> A2) | ws (fp32 -> hs), K=256 ----
    {
        GArgs a0 = { p_beh2, p_Wsb2, bsb, nullptr, p_A2, 256, 256, 256, 4, 2, 2 };
        GArgs a1 = { p_mas2, p_Ws2,  bs,  p_hs,  nullptr, 256, 256, 256, 4, 2, 0 };
        mma_fused3<<<dim3(2, NTOK1 / 128, 2), 256, SMEM_128>>>(a0, a1, a1);
    }
    pred_kernel<<<(NTOK1 * 32 + 255) / 256, 256>>>(p_hs, Wo, bo, out, NTOK1);

    // ---- big GEMM last: fp16, K=256 ----
    {
        GArgs ab = { p_A2, p_B2, bob, out + NTOK1, nullptr, 256, NQP1, NQP1, 4, 1, 0 };
        mma_one<<<dim3(NPAD / 128, NTOK1 / 128), 256, SMEM_128>>>(ab);
    }
}

// round 17
// speedup vs baseline: 2.0784x; 1.0876x over previous
#include <cuda_runtime.h>
#include <cuda_fp16.h>
#include <math.h>
#include <cstdint>

using u32 = unsigned int;
using u64 = unsigned long long;

// Problem constants
#define B_   128
#define T_   200
#define TM1  199
#define NQP1 5001
#define NPAD 5120
#define NTOK  (B_ * T_)    // 25600
#define NTOK1 (B_ * TM1)   // 25472

#define SMEM_128 98304     // 3-stage x (16KB A + 16KB B)

// ---------------------------------------------------------------------------
// Device scratch — ALL GEMM operands plain fp16 [rows, K].
// ---------------------------------------------------------------------------
__device__ __align__(16) __half g_qa2 [(size_t)NTOK  * 256];  // [qe | ae]
__device__ __align__(16) __half g_t12 [(size_t)NTOK  * 128];
__device__ __align__(16) __half g_t22 [(size_t)NTOK  * 128];
__device__ __align__(16) __half g_rk2 [(size_t)NTOK  * 128];
__device__ __align__(16) float g_logits[NTOK  *  64];
__device__ __align__(16) float g_corr  [NTOK  *  64];
__device__ __align__(16) float g_erase [NTOK  * 128];
__device__ __align__(16) float g_add   [NTOK  * 128];
__device__ __align__(16) __half g_beh2[(size_t)NTOK1 * 256];  // [rc | qe_t]
__device__ __align__(16) __half g_mas2[(size_t)NTOK1 * 256];  // [rcn | qe_t1]
__device__ __align__(16) float g_hs    [NTOK1 * 256];
__device__ __align__(16) __half g_A2  [(size_t)NTOK1 * 256];  // tanh(beh@Wsb)
__device__ __align__(16) __half g_B2  [(size_t)NPAD  * 256];  // Wob
// fp16 weights (plain [Npad, K])
__device__ __align__(16) __half g_We2 [128 * 256];
__device__ __align__(16) __half g_Wa2 [128 * 256];
__device__ __align__(16) __half g_We22[128 * 128];
__device__ __align__(16) __half g_Wa22[128 * 128];
__device__ __align__(16) __half g_Wk2 [128 * 128];
__device__ __align__(16) __half g_key2[128 * 128];  // 64 valid rows, rest 0
__device__ __align__(16) __half g_Wsb2[256 * 256];
__device__ __align__(16) __half g_Ws2 [256 * 256];

// ---------------------------------------------------------------------------
// mma helpers (fragment machinery verified rounds 7-16)
// ---------------------------------------------------------------------------
__device__ __forceinline__ void mma_fp16(float c[4], const u32 a[4],
                                         u32 b0, u32 b1)
{
    asm volatile(
        "mma.sync.aligned.m16n8k16.row.col.f32.f16.f16.f32 "
        "{%0,%1,%2,%3}, {%4,%5,%6,%7}, {%8,%9}, {%0,%1,%2,%3};\n"
        : "+f"(c[0]), "+f"(c[1]), "+f"(c[2]), "+f"(c[3])
        : "r"(a[0]), "r"(a[1]), "r"(a[2]), "r"(a[3]), "r"(b0), "r"(b1));
}
__device__ __forceinline__ u32 saddr(const void* p)
{
    return (u32)__cvta_generic_to_shared(p);
}
__device__ __forceinline__ void cp16(u32 d, const void* s)
{
    asm volatile("cp.async.cg.shared.global [%0], [%1], 16;\n" :: "r"(d), "l"(s));
}
// SW128 swizzled byte offset: 16B chunk c (0..7) in a 128B row
__device__ __forceinline__ u32 sw16(int row, int c)
{
    return (u32)(row * 128 + (((c ^ row) & 7) << 4));
}

// Fast activations: MUFU-only paths (approximate rcp; error ~1e-7 rel).
// sigmoid(v) = 1/(1+e^-v); tanh(v) = 1 - 2/(e^{2v}+1)  (NaN-free at +-inf).
__device__ __forceinline__ float fast_sigmoid(float v)
{
    return __fdividef(1.f, 1.f + __expf(-v));
}
__device__ __forceinline__ float fast_tanh(float v)
{
    return 1.f - __fdividef(2.f, __expf(2.f * v) + 1.f);
}
__device__ __forceinline__ float act_f(float v, int ACT)
{
    if (ACT == 1) return fast_sigmoid(v);
    if (ACT == 2) return fast_tanh(v);
    return v;
}

struct GArgs {
    const __half* A;      // [M, lda], K-major
    const __half* B;      // [Npad, NST*64]
    const float* bias;    // [N] or null
    float*  Cf;           // EPI 0 target
    __half* Ch;           // EPI 2 target
    int lda, ldc, N, NST, ACT, EPI;
};

// ---------------------------------------------------------------------------
// 128x128 CTA tile fp16 core. occ 2, 3-stage cp.async, K-chunk 64.
// EPI 0: fp32 store (ldc). EPI 2: fp16 store (ldc).
// ---------------------------------------------------------------------------
__device__ __forceinline__ void mma_core_f16(const GArgs ga, int m0, int n0)
{
    extern __shared__ __half smbuf[];
    const int NST = ga.NST;
    const int KW  = NST * 64;

    const int tid  = threadIdx.x;
    const int lane = tid & 31, wid = tid >> 5;
    const int wm = wid & 1, wn = wid >> 1;

    float acc[4][4][4];
#pragma unroll
    for (int mt = 0; mt < 4; mt++)
#pragma unroll
        for (int nt = 0; nt < 4; nt++)
#pragma unroll
            for (int r = 0; r < 4; r++) acc[mt][nt][r] = 0.f;

    const __half* Ag = ga.A + (size_t)m0 * ga.lda;
    const __half* Bg = ga.B + (size_t)n0 * KW;

    const int lr8 = (lane & 7) + ((lane >> 3) & 1) * 8;
    const int cq  = lane >> 4;

    const u32 ab0 = saddr(smbuf);
    const u32 bb0 = ab0 + 49152;

#define LOAD128(buf, k0)                                                       \
    do {                                                                       \
        u32 ab = ab0 + (buf) * 16384;                                          \
        u32 bb = bb0 + (buf) * 16384;                                          \
        _Pragma("unroll")                                                      \
        for (int i = 0; i < 4; i++) {                                          \
            int g = tid + i * 256;                                             \
            int row = g >> 3, c = g & 7;                                       \
            cp16(ab + sw16(row, c), Ag + (size_t)row * ga.lda + (k0) + c * 8); \
            cp16(bb + sw16(row, c), Bg + (size_t)row * KW + (k0) + c * 8);     \
        }                                                                      \
        asm volatile("cp.async.commit_group;\n");                              \
    } while (0)

    LOAD128(0, 0);
    LOAD128(1, 64);

    for (int st = 0; st < NST; st++) {
        if (st < NST - 1)
            asm volatile("cp.async.wait_group 1;\n");
        else
            asm volatile("cp.async.wait_group 0;\n");
        __syncthreads();
        if (st + 2 < NST)
            LOAD128((st + 2) % 3, (st + 2) * 64);

        const int buf = st % 3;
        const u32 ab = ab0 + buf * 16384;
        const u32 bb = bb0 + buf * 16384;
#pragma unroll
        for (int ks = 0; ks < 4; ks++) {
            const int chv = ks * 2 + cq;
            u32 af[4][4], bq[4][2];
#pragma unroll
            for (int mt = 0; mt < 4; mt++) {
                u32 ad = ab + sw16(wm * 64 + mt * 16 + lr8, chv);
                asm volatile(
                    "ldmatrix.sync.aligned.m8n8.x4.shared.b16 {%0,%1,%2,%3}, [%4];\n"
                    : "=r"(af[mt][0]), "=r"(af[mt][1]),
                      "=r"(af[mt][2]), "=r"(af[mt][3]) : "r"(ad));
            }
#pragma unroll
            for (int bh = 0; bh < 2; bh++) {
                u32 r0, r1, r2, r3;
                u32 ad = bb + sw16(wn * 32 + bh * 16 + lr8, chv);
                asm volatile(
                    "ldmatrix.sync.aligned.m8n8.x4.shared.b16 {%0,%1,%2,%3}, [%4];\n"
                    : "=r"(r0), "=r"(r1), "=r"(r2), "=r"(r3) : "r"(ad));
                bq[bh * 2 + 0][0] = r0; bq[bh * 2 + 0][1] = r2;
                bq[bh * 2 + 1][0] = r1; bq[bh * 2 + 1][1] = r3;
            }
#pragma unroll
            for (int mt = 0; mt < 4; mt++)
#pragma unroll
                for (int nt = 0; nt < 4; nt++)
                    mma_fp16(acc[mt][nt], af[mt], bq[nt][0], bq[nt][1]);
        }
    }
#undef LOAD128

    const int gidr = lane >> 2, tig = lane & 3;
#pragma unroll
    for (int nt = 0; nt < 4; nt++) {
        const int n = n0 + wn * 32 + nt * 8 + tig * 2;
        const bool ok0 = (n < ga.N), ok1 = (n + 1 < ga.N);
        const float bA = (ga.bias != nullptr && ok0) ? ga.bias[n] : 0.f;
        const float bB = (ga.bias != nullptr && ok1) ? ga.bias[n + 1] : 0.f;
#pragma unroll
        for (int mt = 0; mt < 4; mt++) {
            const int m = m0 + wm * 64 + mt * 16 + gidr;
            float v00 = act_f(acc[mt][nt][0] + bA, ga.ACT);
            float v01 = act_f(acc[mt][nt][1] + bB, ga.ACT);
            float v10 = act_f(acc[mt][nt][2] + bA, ga.ACT);
            float v11 = act_f(acc[mt][nt][3] + bB, ga.ACT);
            if (ga.EPI == 0) {
                if (ok0) {
                    ga.Cf[(size_t)m * ga.ldc + n]       = v00;
                    ga.Cf[(size_t)(m + 8) * ga.ldc + n] = v10;
                }
                if (ok1) {
                    ga.Cf[(size_t)m * ga.ldc + n + 1]       = v01;
                    ga.Cf[(size_t)(m + 8) * ga.ldc + n + 1] = v11;
                }
            } else {   // EPI 2: fp16 pair store
                if (ok1) {
                    __half2 p0; p0.x = __float2half(v00); p0.y = __float2half(v01);
                    __half2 p1; p1.x = __float2half(v10); p1.y = __float2half(v11);
                    *reinterpret_cast<__half2*>(&ga.Ch[(size_t)m * ga.ldc + n])       = p0;
                    *reinterpret_cast<__half2*>(&ga.Ch[(size_t)(m + 8) * ga.ldc + n]) = p1;
                }
            }
        }
    }
}

__global__ void __launch_bounds__(256, 2) mma_one(GArgs ga)
{
    mma_core_f16(ga, blockIdx.y * 128, blockIdx.x * 128);
}

__global__ void __launch_bounds__(256, 2) mma_fused3(GArgs a0, GArgs a1, GArgs a2)
{
    GArgs ga = (blockIdx.z == 0) ? a0 : (blockIdx.z == 1) ? a1 : a2;
    mma_core_f16(ga, blockIdx.y * 128, blockIdx.x * 128);
}

// ---------------------------------------------------------------------------
// Batched weight conversion to fp16 (8 small weights, one launch)
// ---------------------------------------------------------------------------
struct WConvArgs {
    const float* src[8];
    __half*      dst[8];
    int Nw[8];      // valid rows (rest zeroed)
    int K[8];
    int total[8];   // NwPad * K
};

__global__ void convW_all_kernel(WConvArgs wa)
{
    int z   = blockIdx.y;
    int idx = blockIdx.x * 256 + threadIdx.x;
    if (idx >= wa.total[z]) return;
    int K = wa.K[z];
    int r = idx / K, c = idx - r * K;
    float x = (r < wa.Nw[z]) ? wa.src[z][(size_t)r * K + c] : 0.f;
    wa.dst[z][(size_t)r * K + c] = __float2half(x);
}

// Wob -> fp16 [NPAD][256]
__global__ void convWob_f16(const float* __restrict__ X, __half* __restrict__ Y)
{
    int idx = blockIdx.x * 256 + threadIdx.x;
    int r = idx >> 8, c = idx & 255;
    float x = (r < NQP1) ? X[(size_t)r * 256 + c] : 0.f;
    Y[(size_t)r * 256 + c] = __float2half(x);
}

// ---------------------------------------------------------------------------
// Gather -> qa2 [NTOK,256] fp16 (qe = cols 0..127, ae = cols 128..255)
// ---------------------------------------------------------------------------
__global__ void gather2_kernel(const int* __restrict__ q, const int* __restrict__ a,
                               const float* __restrict__ qet, const float* __restrict__ aet,
                               __half* __restrict__ qa2)
{
    int tok = blockIdx.x;
    int i   = threadIdx.x;
    float v = (i < 128) ? qet[(size_t)q[tok] * 128 + i]
                        : aet[(size_t)a[tok] * 128 + (i - 128)];
    qa2[(size_t)tok * 256 + i] = __float2half(v);
}

// qe-halves of beh2/mas2: plain copies from qa2
__global__ void qecopy2_kernel(const __half* __restrict__ qa2,
                               __half* __restrict__ beh2, __half* __restrict__ mas2)
{
    int tok = blockIdx.x;          // 0..NTOK1-1
    int c   = threadIdx.x;         // 0..127
    int b   = tok / TM1;
    int t   = tok - b * TM1;
    size_t r0 = (size_t)(b * T_ + t) * 256;
    size_t o  = (size_t)tok * 256;
    beh2[o + 128 + c] = qa2[r0 + c];
    mas2[o + 128 + c] = qa2[r0 + 256 + c];   // token t+1 qe
}

// ---------------------------------------------------------------------------
// softmax (verified)
// ---------------------------------------------------------------------------
__global__ void softmax64_kernel(const float* __restrict__ lg, float* __restrict__ co,
                                 int ntok)
{
    int g    = blockIdx.x * blockDim.x + threadIdx.x;
    int w    = g >> 5;
    int lane = g & 31;
    if (w >= ntok) return;
    const float* L = lg + (size_t)w * 64;
    float v0 = L[lane], v1 = L[lane + 32];
    float mx = fmaxf(v0, v1);
#pragma unroll
    for (int o = 16; o; o >>= 1) mx = fmaxf(mx, __shfl_xor_sync(0xffffffffu, mx, o));
    float e0 = __expf(v0 - mx), e1 = __expf(v1 - mx);
    float s = e0 + e1;
#pragma unroll
    for (int o = 16; o; o >>= 1) s += __shfl_xor_sync(0xffffffffu, s, o);
    float inv = __fdividef(1.f, s);
    co[(size_t)w * 64 + lane]      = e0 * inv;
    co[(size_t)w * 64 + lane + 32] = e1 * inv;
}

// ---------------------------------------------------------------------------
// Sequential scan (fp32 internal); writes rc/rcn as fp16 into beh2/mas2
// ---------------------------------------------------------------------------
__global__ void __launch_bounds__(256) scan_kernel(
    const float* __restrict__ corr, const float* __restrict__ er,
    const float* __restrict__ ad,   const float* __restrict__ vinit,
    __half* __restrict__ beh2, __half* __restrict__ mas2)
{
    int b   = blockIdx.x;
    int tid = threadIdx.x;
    int v   = tid & 127;
    int cg  = tid >> 7;

    float M[32];
#pragma unroll
    for (int i = 0; i < 32; i++) M[i] = vinit[(size_t)(cg * 32 + i) * 128 + v];

    __shared__ float sw[64], swn[64], s_rc[128], s_rcn[128];

    const float* corr_b = corr + (size_t)b * T_ * 64;
    const float* er_b   = er   + (size_t)b * T_ * 128;
    const float* ad_b   = ad   + (size_t)b * T_ * 128;

    float ev_n = er_b[v];
    float av_n = ad_b[v];

    for (int t = 0; t < TM1; t++) {
        float ev = ev_n, av = av_n;
        if (t + 1 < TM1) {
            ev_n = er_b[(size_t)(t + 1) * 128 + v];
            av_n = ad_b[(size_t)(t + 1) * 128 + v];
        }
        if (tid < 64)       sw[tid]       = corr_b[(size_t)t * 64 + tid];
        else if (tid < 128) swn[tid - 64] = corr_b[(size_t)(t + 1) * 64 + (tid - 64)];
        __syncthreads();

        float prc = 0.f, prcn = 0.f;
#pragma unroll
        for (int i = 0; i < 32; i++) {
            float wc = sw[cg * 32 + i];
            float m  = fmaf(wc, av, M[i] * (1.f - wc * ev));
            M[i] = m;
            prc  = fmaf(wc, m, prc);
            prcn = fmaf(swn[cg * 32 + i], m, prcn);
        }
        if (cg == 0) { s_rc[v] = prc; s_rcn[v] = prcn; }
        __syncthreads();
        if (cg == 1) {
            float vb = s_rc[v]  + prc;
            float vm = s_rcn[v] + prcn;
            size_t o = (size_t)(b * TM1 + t) * 256;
            beh2[o + v] = __float2half(vb);
            mas2[o + v] = __float2half(vm);
        }
        __syncthreads();
    }
}

__global__ void pred_kernel(const float* __restrict__ hs, const float* __restrict__ Wo,
                            const float* __restrict__ bo, float* __restrict__ out, int ntok)
{
    int g    = blockIdx.x * blockDim.x + threadIdx.x;
    int w    = g >> 5;
    int lane = g & 31;
    if (w >= ntok) return;
    const float* h = hs + (size_t)w * 256;
    float s = 0.f;
#pragma unroll
    for (int j = 0; j < 8; j++) s = fmaf(h[lane + j * 32], Wo[lane + j * 32], s);
#pragma unroll
    for (int o = 16; o; o >>= 1) s += __shfl_xor_sync(0xffffffffu, s, o);
    if (lane == 0) out[w] = fast_sigmoid(s + bo[0]);
}

// ---------------------------------------------------------------------------
// Launch
// ---------------------------------------------------------------------------
extern "C" void kernel_launch(void* const* d_in, const int* in_sizes, int n_in,
                              void* d_out, int out_size)
{
    (void)in_sizes; (void)n_in; (void)out_size;

    const int*   q_data     = (const int*)  d_in[0];
    const int*   a_data     = (const int*)  d_in[1];
    const float* q_embed    = (const float*)d_in[2];
    const float* a_embed    = (const float*)d_in[3];
    const float* key_matrix = (const float*)d_in[4];
    const float* value_init = (const float*)d_in[5];
    const float* Wk  = (const float*)d_in[6];   const float* bk  = (const float*)d_in[7];
    const float* We  = (const float*)d_in[8];   const float* be  = (const float*)d_in[9];
    const float* We2 = (const float*)d_in[10];  const float* be2 = (const float*)d_in[11];
    const float* Wa  = (const float*)d_in[12];  const float* ba  = (const float*)d_in[13];
    const float* Wa2 = (const float*)d_in[14];  const float* ba2 = (const float*)d_in[15];
    const float* Ws  = (const float*)d_in[16];  const float* bs  = (const float*)d_in[17];
    const float* Wo  = (const float*)d_in[18];  const float* bo  = (const float*)d_in[19];
    const float* Wsb = (const float*)d_in[20];  const float* bsb = (const float*)d_in[21];
    const float* Wob = (const float*)d_in[22];  const float* bob = (const float*)d_in[23];
    float* out = (float*)d_out;

    __half *p_qa2, *p_t12, *p_t22, *p_rk2, *p_beh2, *p_mas2, *p_A2, *p_B2;
    __half *p_We2, *p_Wa2, *p_We22, *p_Wa22, *p_Wk2, *p_key2, *p_Wsb2, *p_Ws2;
    float *p_log, *p_corr, *p_er, *p_ad, *p_hs;
    cudaGetSymbolAddress((void**)&p_qa2,  g_qa2);
    cudaGetSymbolAddress((void**)&p_t12,  g_t12);
    cudaGetSymbolAddress((void**)&p_t22,  g_t22);
    cudaGetSymbolAddress((void**)&p_rk2,  g_rk2);
    cudaGetSymbolAddress((void**)&p_log,  g_logits);
    cudaGetSymbolAddress((void**)&p_corr, g_corr);
    cudaGetSymbolAddress((void**)&p_er,   g_erase);
    cudaGetSymbolAddress((void**)&p_ad,   g_add);
    cudaGetSymbolAddress((void**)&p_beh2, g_beh2);
    cudaGetSymbolAddress((void**)&p_mas2, g_mas2);
    cudaGetSymbolAddress((void**)&p_hs,   g_hs);
    cudaGetSymbolAddress((void**)&p_A2,   g_A2);
    cudaGetSymbolAddress((void**)&p_B2,   g_B2);
    cudaGetSymbolAddress((void**)&p_We2,  g_We2);
    cudaGetSymbolAddress((void**)&p_Wa2,  g_Wa2);
    cudaGetSymbolAddress((void**)&p_We22, g_We22);
    cudaGetSymbolAddress((void**)&p_Wa22, g_Wa22);
    cudaGetSymbolAddress((void**)&p_Wk2,  g_Wk2);
    cudaGetSymbolAddress((void**)&p_key2, g_key2);
    cudaGetSymbolAddress((void**)&p_Wsb2, g_Wsb2);
    cudaGetSymbolAddress((void**)&p_Ws2,  g_Ws2);

    cudaFuncSetAttribute(mma_one,    cudaFuncAttributeMaxDynamicSharedMemorySize, SMEM_128);
    cudaFuncSetAttribute(mma_fused3, cudaFuncAttributeMaxDynamicSharedMemorySize, SMEM_128);

    // ---- weight conversions ----
    {
        WConvArgs wa;
        wa.src[0] = We;  wa.dst[0] = p_We2;  wa.Nw[0] = 128; wa.K[0] = 256; wa.total[0] = 128 * 256;
        wa.src[1] = Wa;  wa.dst[1] = p_Wa2;  wa.Nw[1] = 128; wa.K[1] = 256; wa.total[1] = 128 * 256;
        wa.src[2] = We2; wa.dst[2] = p_We22; wa.Nw[2] = 128; wa.K[2] = 128; wa.total[2] = 128 * 128;
        wa.src[3] = Wa2; wa.dst[3] = p_Wa22; wa.Nw[3] = 128; wa.K[3] = 128; wa.total[3] = 128 * 128;
        wa.src[4] = Wk;  wa.dst[4] = p_Wk2;  wa.Nw[4] = 128; wa.K[4] = 128; wa.total[4] = 128 * 128;
        wa.src[5] = key_matrix; wa.dst[5] = p_key2; wa.Nw[5] = 64; wa.K[5] = 128; wa.total[5] = 128 * 128;
        wa.src[6] = Wsb; wa.dst[6] = p_Wsb2; wa.Nw[6] = 256; wa.K[6] = 256; wa.total[6] = 256 * 256;
        wa.src[7] = Ws;  wa.dst[7] = p_Ws2;  wa.Nw[7] = 256; wa.K[7] = 256; wa.total[7] = 256 * 256;
        convW_all_kernel<<<dim3(256, 8), 256>>>(wa);
    }
    convWob_f16<<<NPAD * 256 / 256, 256>>>(Wob, p_B2);

    // ---- gather + qe-halves of beh2/mas2 ----
    gather2_kernel<<<NTOK, 256>>>(q_data, a_data, q_embed, a_embed, p_qa2);
    qecopy2_kernel<<<NTOK1, 128>>>(p_qa2, p_beh2, p_mas2);

    // ---- stage A: t1 | t2 | rk (all fp16, K=256/256/128) ----
    {
        GArgs a0 = { p_qa2, p_We2, be, nullptr, p_t12, 256, 128, 128, 4, 0, 2 };
        GArgs a1 = { p_qa2, p_Wa2, ba, nullptr, p_t22, 256, 128, 128, 4, 0, 2 };
        GArgs a2 = { p_qa2, p_Wk2, bk, nullptr, p_rk2, 256, 128, 128, 2, 0, 2 };
        mma_fused3<<<dim3(1, NTOK / 128, 3), 256, SMEM_128>>>(a0, a1, a2);
    }
    // ---- stage A: er | ad | logits (K=128) ----
    {
        GArgs a0 = { p_t12, p_We22, be2, p_er,  nullptr, 128, 128, 128, 2, 1, 0 };
        GArgs a1 = { p_t22, p_Wa22, ba2, p_ad,  nullptr, 128, 128, 128, 2, 2, 0 };
        GArgs a2 = { p_rk2, p_key2, nullptr, p_log, nullptr, 128, 64, 64, 2, 0, 0 };
        mma_fused3<<<dim3(1, NTOK / 128, 3), 256, SMEM_128>>>(a0, a1, a2);
    }
    softmax64_kernel<<<(NTOK * 32 + 255) / 256, 256>>>(p_log, p_corr, NTOK);

    // ---- stage B: scan writes rc/rcn halves of beh2/mas2 ----
    scan_kernel<<<B_, 256>>>(p_corr, p_er, p_ad, value_init, p_beh2, p_mas2);

    // ---- stage C: wsb (fp16 -> A2) | ws (fp32 -> hs), K=256 ----
    {
        GArgs a0 = { p_beh2, p_Wsb2, bsb, nullptr, p_A2, 256, 256, 256, 4, 2, 2 };
        GArgs a1 = { p_mas2, p_Ws2,  bs,  p_hs,  nullptr, 256, 256, 256, 4, 2, 0 };
        mma_fused3<<<dim3(2, NTOK1 / 128, 2), 256, SMEM_128>>>(a0, a1, a1);
    }
    pred_kernel<<<(NTOK1 * 32 + 255) / 256, 256>>>(p_hs, Wo, bo, out, NTOK1);

    // ---- big GEMM last: fp16, K=256 ----
    {
        GArgs ab = { p_A2, p_B2, bob, out + NTOK1, nullptr, 256, NQP1, NQP1, 4, 1, 0 };
        mma_one<<<dim3(NPAD / 128, NTOK1 / 128), 256, SMEM_128>>>(ab);
    }
}